// round 2
// baseline (speedup 1.0000x reference)
#include <cuda_runtime.h>
#include <math.h>

#define BB 2
#define TT 2048
#define DM 1024
#define NQ 2688   // 4*32 + 8*64 + 16*128
#define NK 224    // 32 + 64 + 128
#define NW 28     // 4 + 8 + 16

// Scratch (device globals: no allocation allowed)
__device__ float g_mean[BB * DM];
__device__ float g_std[BB * DM];
__device__ float g_probs[BB * TT * 3];
__device__ float g_Q[(size_t)BB * TT * NQ];   // ~44 MB
__device__ float g_K[(size_t)BB * TT * NK];
__device__ float g_Wp[(size_t)BB * TT * NW];

// ---------------------------------------------------------------------------
// 1) per-(b,d) mean / unbiased std over T
// ---------------------------------------------------------------------------
__global__ void stats_kernel(const float* __restrict__ x) {
    int d = blockIdx.x * blockDim.x + threadIdx.x;
    int b = blockIdx.y;
    const float* px = x + (size_t)b * TT * DM + d;
    double s = 0.0, s2 = 0.0;
    for (int t = 0; t < TT; t++) {
        double v = (double)px[(size_t)t * DM];
        s += v; s2 += v * v;
    }
    double m = s / (double)TT;
    double var = (s2 - s * s / (double)TT) / (double)(TT - 1);
    if (var < 0.0) var = 0.0;
    g_mean[b * DM + d] = (float)m;
    g_std[b * DM + d] = (float)sqrt(var);
}

// ---------------------------------------------------------------------------
// 2) selector MLP + softmax -> g_probs[b*T+t][3]
//    feats = x + mean[b,:] + std[b,:] + (t/T)*0.1
// ---------------------------------------------------------------------------
__global__ void selector_kernel(const float* __restrict__ x,
                                const float* __restrict__ w1, const float* __restrict__ b1,
                                const float* __restrict__ w2, const float* __restrict__ b2,
                                const float* __restrict__ w3, const float* __restrict__ b3) {
    __shared__ float feats[DM];
    __shared__ float h1[64];
    __shared__ float h2[64];
    __shared__ float lg[3];
    int row = blockIdx.x;
    int b = row / TT;
    int t = row % TT;
    int tid = threadIdx.x;
    float posv = 0.1f * ((float)t / (float)TT);

    for (int i = tid; i < DM; i += 256)
        feats[i] = x[(size_t)row * DM + i] + g_mean[b * DM + i] + g_std[b * DM + i] + posv;
    __syncthreads();

    int warp = tid >> 5, lane = tid & 31;
    for (int j = warp; j < 64; j += 8) {
        const float* wr = w1 + j * DM;
        float a = 0.f;
        for (int i = lane; i < DM; i += 32) a += feats[i] * wr[i];
        #pragma unroll
        for (int o = 16; o; o >>= 1) a += __shfl_down_sync(0xffffffffu, a, o);
        if (lane == 0) h1[j] = fmaxf(a + b1[j], 0.f);
    }
    __syncthreads();
    for (int j = warp; j < 64; j += 8) {
        const float* wr = w2 + j * 64;
        float a = h1[lane] * wr[lane] + h1[lane + 32] * wr[lane + 32];
        #pragma unroll
        for (int o = 16; o; o >>= 1) a += __shfl_down_sync(0xffffffffu, a, o);
        if (lane == 0) h2[j] = fmaxf(a + b2[j], 0.f);
    }
    __syncthreads();
    if (tid < 3) {
        float a = b3[tid];
        #pragma unroll 8
        for (int i = 0; i < 64; i++) a += h2[i] * w3[tid * 64 + i];
        lg[tid] = a;
    }
    __syncthreads();
    if (tid == 0) {
        float m = fmaxf(lg[0], fmaxf(lg[1], lg[2]));
        float e0 = expf(lg[0] - m), e1 = expf(lg[1] - m), e2 = expf(lg[2] - m);
        float inv = 1.f / (e0 + e1 + e2);
        g_probs[row * 3 + 0] = e0 * inv;
        g_probs[row * 3 + 1] = e1 * inv;
        g_probs[row * 3 + 2] = e2 * inv;
    }
}

// ---------------------------------------------------------------------------
// 3) projection GEMM: out[m, colOff+n] = sum_k X[m,k] * W[n,k]
//    M = BB*TT = 4096 (full), K = 1024, which selects g_Q / g_K / g_Wp
// ---------------------------------------------------------------------------
#define BM 64
#define BN 64
#define BKC 32

__global__ void __launch_bounds__(256, 2)
proj_gemm(const float* __restrict__ X, const float* __restrict__ Wt,
          int N, int which, int ldOut, int colOff) {
    __shared__ float As[BKC][BM + 4];
    __shared__ float Bs[BKC][BN + 4];
    int m0 = blockIdx.x * BM, n0 = blockIdx.y * BN;
    int tid = threadIdx.x;
    int tx = tid & 15, ty = tid >> 4;
    float acc[4][4] = {};

    for (int k0 = 0; k0 < DM; k0 += BKC) {
        #pragma unroll
        for (int l = 0; l < 2; l++) {
            int idx = tid + l * 256;     // 0..511
            int m = idx & 63;
            int kg = idx >> 6;           // 0..7 (4 floats each)
            float4 v = *(const float4*)(X + (size_t)(m0 + m) * DM + k0 + kg * 4);
            As[kg * 4 + 0][m] = v.x; As[kg * 4 + 1][m] = v.y;
            As[kg * 4 + 2][m] = v.z; As[kg * 4 + 3][m] = v.w;
            float4 w = make_float4(0.f, 0.f, 0.f, 0.f);
            if (n0 + m < N)
                w = *(const float4*)(Wt + (size_t)(n0 + m) * DM + k0 + kg * 4);
            Bs[kg * 4 + 0][m] = w.x; Bs[kg * 4 + 1][m] = w.y;
            Bs[kg * 4 + 2][m] = w.z; Bs[kg * 4 + 3][m] = w.w;
        }
        __syncthreads();
        #pragma unroll
        for (int k = 0; k < BKC; k++) {
            float4 av = *(const float4*)&As[k][ty * 4];
            float4 bv = *(const float4*)&Bs[k][tx * 4];
            float ar[4] = {av.x, av.y, av.z, av.w};
            float br[4] = {bv.x, bv.y, bv.z, bv.w};
            #pragma unroll
            for (int i = 0; i < 4; i++)
                #pragma unroll
                for (int j = 0; j < 4; j++)
                    acc[i][j] += ar[i] * br[j];
        }
        __syncthreads();
    }

    float* out = (which == 0) ? g_Q : (which == 1) ? g_K : g_Wp;
    #pragma unroll
    for (int i = 0; i < 4; i++) {
        int m = m0 + ty * 4 + i;
        #pragma unroll
        for (int j = 0; j < 4; j++) {
            int n = n0 + tx * 4 + j;
            if (n < N) out[(size_t)m * ldOut + colOff + n] = acc[i][j];
        }
    }
}

// ---------------------------------------------------------------------------
// 4) attention: final[b,t,s] = sum_gh wp[t,gh] * relu( Q_gh[t,:] . K_gh[s,:] )
//    wp[t,gh] = probs[t, cfg(gh)] * Wproj[t, gh]
//    64x64 output tile per block; loop 28 heads, k-chunks of 32.
// ---------------------------------------------------------------------------
__global__ void __launch_bounds__(256, 2)
attn_kernel(float* __restrict__ out) {
    __shared__ float Qs[BKC][BM + 4];
    __shared__ float Ks[BKC][BN + 4];
    __shared__ float wp[64][NW];

    int b = blockIdx.z;
    int t0 = blockIdx.x * 64;
    int s0 = blockIdx.y * 64;
    int tid = threadIdx.x;
    int tx = tid & 15, ty = tid >> 4;

    for (int idx = tid; idx < 64 * NW; idx += 256) {
        int tt = idx / NW, gh = idx % NW;
        int cfg = (gh < 4) ? 0 : (gh < 12) ? 1 : 2;
        int row = b * TT + t0 + tt;
        wp[tt][gh] = g_probs[row * 3 + cfg] * g_Wp[(size_t)row * NW + gh];
    }
    __syncthreads();

    float acc[4][4] = {};

    #pragma unroll 1
    for (int gh = 0; gh < NW; gh++) {
        int dh, qoff, koff;
        if (gh < 4)       { dh = 32;  qoff = gh * 32;              koff = 0;  }
        else if (gh < 12) { dh = 64;  qoff = 128 + (gh - 4) * 64;  koff = 32; }
        else              { dh = 128; qoff = 640 + (gh - 12) * 128; koff = 96; }

        float dot[4][4] = {};

        #pragma unroll 1
        for (int kb = 0; kb < dh; kb += BKC) {
            #pragma unroll
            for (int l = 0; l < 2; l++) {
                int idx = tid + l * 256;
                int m = idx & 63;
                int kg = idx >> 6;
                float4 vq = *(const float4*)(g_Q + (size_t)(b * TT + t0 + m) * NQ + qoff + kb + kg * 4);
                Qs[kg * 4 + 0][m] = vq.x; Qs[kg * 4 + 1][m] = vq.y;
                Qs[kg * 4 + 2][m] = vq.z; Qs[kg * 4 + 3][m] = vq.w;
                float4 vk = *(const float4*)(g_K + (size_t)(b * TT + s0 + m) * NK + koff + kb + kg * 4);
                Ks[kg * 4 + 0][m] = vk.x; Ks[kg * 4 + 1][m] = vk.y;
                Ks[kg * 4 + 2][m] = vk.z; Ks[kg * 4 + 3][m] = vk.w;
            }
            __syncthreads();
            #pragma unroll
            for (int k = 0; k < BKC; k++) {
                float4 av = *(const float4*)&Qs[k][ty * 4];
                float4 bv = *(const float4*)&Ks[k][tx * 4];
                float ar[4] = {av.x, av.y, av.z, av.w};
                float br[4] = {bv.x, bv.y, bv.z, bv.w};
                #pragma unroll
                for (int i = 0; i < 4; i++)
                    #pragma unroll
                    for (int j = 0; j < 4; j++)
                        dot[i][j] += ar[i] * br[j];
            }
            __syncthreads();
        }

        #pragma unroll
        for (int i = 0; i < 4; i++) {
            float wgt = wp[ty * 4 + i][gh];
            #pragma unroll
            for (int j = 0; j < 4; j++)
                acc[i][j] += wgt * fmaxf(dot[i][j], 0.f);
        }
    }

    #pragma unroll
    for (int i = 0; i < 4; i++) {
        size_t r = (size_t)(b * TT + t0 + ty * 4 + i) * TT;
        #pragma unroll
        for (int j = 0; j < 4; j++)
            out[r + s0 + tx * 4 + j] = acc[i][j];
    }
}

// ---------------------------------------------------------------------------
extern "C" void kernel_launch(void* const* d_in, const int* in_sizes, int n_in,
                              void* d_out, int out_size) {
    const float* x   = (const float*)d_in[0];
    const float* w1  = (const float*)d_in[1];
    const float* b1  = (const float*)d_in[2];
    const float* w2  = (const float*)d_in[3];
    const float* b2  = (const float*)d_in[4];
    const float* w3  = (const float*)d_in[5];
    const float* b3  = (const float*)d_in[6];
    const float* qw0 = (const float*)d_in[7];
    const float* kw0 = (const float*)d_in[8];
    const float* ww0 = (const float*)d_in[9];
    const float* qw1 = (const float*)d_in[10];
    const float* kw1 = (const float*)d_in[11];
    const float* ww1 = (const float*)d_in[12];
    const float* qw2 = (const float*)d_in[13];
    const float* kw2 = (const float*)d_in[14];
    const float* ww2 = (const float*)d_in[15];
    float* out = (float*)d_out;

    stats_kernel<<<dim3(DM / 256, BB), 256>>>(x);
    selector_kernel<<<BB * TT, 256>>>(x, w1, b1, w2, b2, w3, b3);

    // Q projections -> g_Q (ld = 2688), column offsets 0 / 128 / 640
    proj_gemm<<<dim3(64, 2), 256>>>(x, qw0, 128, 0, NQ, 0);
    proj_gemm<<<dim3(64, 8), 256>>>(x, qw1, 512, 0, NQ, 128);
    proj_gemm<<<dim3(64, 32), 256>>>(x, qw2, 2048, 0, NQ, 640);
    // K projections -> g_K (ld = 224), offsets 0 / 32 / 96
    proj_gemm<<<dim3(64, 1), 256>>>(x, kw0, 32, 1, NK, 0);
    proj_gemm<<<dim3(64, 1), 256>>>(x, kw1, 64, 1, NK, 32);
    proj_gemm<<<dim3(64, 2), 256>>>(x, kw2, 128, 1, NK, 96);
    // W projections -> g_Wp (ld = 28), offsets 0 / 4 / 12
    proj_gemm<<<dim3(64, 1), 256>>>(x, ww0, 4, 2, NW, 0);
    proj_gemm<<<dim3(64, 1), 256>>>(x, ww1, 8, 2, NW, 4);
    proj_gemm<<<dim3(64, 2), 256>>>(x, ww2, 16, 2, NW, 12);

    attn_kernel<<<dim3(TT / 64, TT / 64, BB), 256>>>(out);
}

// round 5
// speedup vs baseline: 1.5577x; 1.5577x over previous
#include <cuda_runtime.h>
#include <cuda_bf16.h>
#include <math.h>
#include <stdint.h>

#define BB 2
#define TT 2048
#define DM 1024
#define NQ 2688   // 4*32 + 8*64 + 16*128
#define NK 224    // 32 + 64 + 128
#define NW 28     // 4 + 8 + 16

// ---------------- device scratch (no allocation allowed) --------------------
__device__ float g_mean[BB * DM];
__device__ float g_std[BB * DM];
__device__ float g_probs[BB * TT * 3];
__device__ float g_Wp[(size_t)BB * TT * NW];
__device__ __align__(256) __nv_bfloat16 g_Qhi[(size_t)BB * TT * NQ];
__device__ __align__(256) __nv_bfloat16 g_Qlo[(size_t)BB * TT * NQ];
__device__ __align__(256) __nv_bfloat16 g_Khi[(size_t)BB * TT * NK];
__device__ __align__(256) __nv_bfloat16 g_Klo[(size_t)BB * TT * NK];

// ---------------- portable PTX helpers (no sm_103a-only instructions) -------
__device__ __forceinline__ uint32_t smem_u32_of(const void* p) {
    uint32_t a;
    asm("{ .reg .u64 t; cvta.to.shared.u64 t, %1; cvt.u32.u64 %0, t; }" : "=r"(a) : "l"(p));
    return a;
}
#define CPASYNC16(s, g) \
    asm volatile("cp.async.cg.shared.global [%0], [%1], 16;" :: "r"(s), "l"(g))
#define CPCOMMIT() asm volatile("cp.async.commit_group;" ::: "memory")
#define CPWAIT0()  asm volatile("cp.async.wait_group 0;" ::: "memory")
#define LDSM4(r0, r1, r2, r3, addr) \
    asm volatile("ldmatrix.sync.aligned.m8n8.x4.shared.b16 {%0,%1,%2,%3}, [%4];" \
                 : "=r"(r0), "=r"(r1), "=r"(r2), "=r"(r3) : "r"(addr))
#define MMA16816(d0, d1, d2, d3, a0, a1, a2, a3, b0, b1) \
    asm volatile("mma.sync.aligned.m16n8k16.row.col.f32.bf16.bf16.f32 " \
                 "{%0,%1,%2,%3}, {%4,%5,%6,%7}, {%8,%9}, {%0,%1,%2,%3};" \
                 : "+f"(d0), "+f"(d1), "+f"(d2), "+f"(d3) \
                 : "r"(a0), "r"(a1), "r"(a2), "r"(a3), "r"(b0), "r"(b1))

// ---------------------------------------------------------------------------
// 1) per-(b,d) mean / unbiased std over T
// ---------------------------------------------------------------------------
__global__ void stats_kernel(const float* __restrict__ x) {
    int d = blockIdx.x * blockDim.x + threadIdx.x;
    int b = blockIdx.y;
    const float* px = x + (size_t)b * TT * DM + d;
    double s = 0.0, s2 = 0.0;
    for (int t = 0; t < TT; t++) {
        double v = (double)px[(size_t)t * DM];
        s += v; s2 += v * v;
    }
    double m = s / (double)TT;
    double var = (s2 - s * s / (double)TT) / (double)(TT - 1);
    if (var < 0.0) var = 0.0;
    g_mean[b * DM + d] = (float)m;
    g_std[b * DM + d] = (float)sqrt(var);
}

// ---------------------------------------------------------------------------
// 2) selector MLP + softmax
// ---------------------------------------------------------------------------
__global__ void selector_kernel(const float* __restrict__ x,
                                const float* __restrict__ w1, const float* __restrict__ b1,
                                const float* __restrict__ w2, const float* __restrict__ b2,
                                const float* __restrict__ w3, const float* __restrict__ b3) {
    __shared__ float feats[DM];
    __shared__ float h1[64];
    __shared__ float h2[64];
    __shared__ float lg[3];
    int row = blockIdx.x;
    int b = row / TT;
    int t = row % TT;
    int tid = threadIdx.x;
    float posv = 0.1f * ((float)t / (float)TT);

    for (int i = tid; i < DM; i += 256)
        feats[i] = x[(size_t)row * DM + i] + g_mean[b * DM + i] + g_std[b * DM + i] + posv;
    __syncthreads();

    int warp = tid >> 5, lane = tid & 31;
    for (int j = warp; j < 64; j += 8) {
        const float* wr = w1 + j * DM;
        float a = 0.f;
        for (int i = lane; i < DM; i += 32) a += feats[i] * wr[i];
        #pragma unroll
        for (int o = 16; o; o >>= 1) a += __shfl_down_sync(0xffffffffu, a, o);
        if (lane == 0) h1[j] = fmaxf(a + b1[j], 0.f);
    }
    __syncthreads();
    for (int j = warp; j < 64; j += 8) {
        const float* wr = w2 + j * 64;
        float a = h1[lane] * wr[lane] + h1[lane + 32] * wr[lane + 32];
        #pragma unroll
        for (int o = 16; o; o >>= 1) a += __shfl_down_sync(0xffffffffu, a, o);
        if (lane == 0) h2[j] = fmaxf(a + b2[j], 0.f);
    }
    __syncthreads();
    if (tid < 3) {
        float a = b3[tid];
        #pragma unroll 8
        for (int i = 0; i < 64; i++) a += h2[i] * w3[tid * 64 + i];
        lg[tid] = a;
    }
    __syncthreads();
    if (tid == 0) {
        float m = fmaxf(lg[0], fmaxf(lg[1], lg[2]));
        float e0 = expf(lg[0] - m), e1 = expf(lg[1] - m), e2 = expf(lg[2] - m);
        float inv = 1.f / (e0 + e1 + e2);
        g_probs[row * 3 + 0] = e0 * inv;
        g_probs[row * 3 + 1] = e1 * inv;
        g_probs[row * 3 + 2] = e2 * inv;
    }
}

// ---------------------------------------------------------------------------
// 3) projection GEMM (FFMA), emitting bf16 hi/lo for Q (which=0), K (which=1)
//    and fp32 for the head weights (which=2)
// ---------------------------------------------------------------------------
#define BM 64
#define BN 64
#define BKC 32

__global__ void __launch_bounds__(256, 2)
proj_gemm(const float* __restrict__ X, const float* __restrict__ Wt,
          int N, int which, int ldOut, int colOff) {
    __shared__ float As[BKC][BM + 4];
    __shared__ float Bs[BKC][BN + 4];
    int m0 = blockIdx.x * BM, n0 = blockIdx.y * BN;
    int tid = threadIdx.x;
    int tx = tid & 15, ty = tid >> 4;
    float acc[4][4] = {};

    for (int k0 = 0; k0 < DM; k0 += BKC) {
        #pragma unroll
        for (int l = 0; l < 2; l++) {
            int idx = tid + l * 256;
            int m = idx & 63;
            int kg = idx >> 6;
            float4 v = *(const float4*)(X + (size_t)(m0 + m) * DM + k0 + kg * 4);
            As[kg * 4 + 0][m] = v.x; As[kg * 4 + 1][m] = v.y;
            As[kg * 4 + 2][m] = v.z; As[kg * 4 + 3][m] = v.w;
            float4 w = make_float4(0.f, 0.f, 0.f, 0.f);
            if (n0 + m < N)
                w = *(const float4*)(Wt + (size_t)(n0 + m) * DM + k0 + kg * 4);
            Bs[kg * 4 + 0][m] = w.x; Bs[kg * 4 + 1][m] = w.y;
            Bs[kg * 4 + 2][m] = w.z; Bs[kg * 4 + 3][m] = w.w;
        }
        __syncthreads();
        #pragma unroll
        for (int k = 0; k < BKC; k++) {
            float4 av = *(const float4*)&As[k][ty * 4];
            float4 bv = *(const float4*)&Bs[k][tx * 4];
            float ar[4] = {av.x, av.y, av.z, av.w};
            float br[4] = {bv.x, bv.y, bv.z, bv.w};
            #pragma unroll
            for (int i = 0; i < 4; i++)
                #pragma unroll
                for (int j = 0; j < 4; j++)
                    acc[i][j] += ar[i] * br[j];
        }
        __syncthreads();
    }

    #pragma unroll
    for (int i = 0; i < 4; i++) {
        int m = m0 + ty * 4 + i;
        #pragma unroll
        for (int j = 0; j < 4; j++) {
            int n = n0 + tx * 4 + j;
            if (n >= N) continue;
            float v = acc[i][j];
            if (which == 0) {
                __nv_bfloat16 h = __float2bfloat16(v);
                size_t o = (size_t)m * NQ + colOff + n;
                g_Qhi[o] = h;
                g_Qlo[o] = __float2bfloat16(v - __bfloat162float(h));
            } else if (which == 1) {
                __nv_bfloat16 h = __float2bfloat16(v);
                size_t o = (size_t)m * NK + colOff + n;
                g_Khi[o] = h;
                g_Klo[o] = __float2bfloat16(v - __bfloat162float(h));
            } else {
                g_Wp[(size_t)m * NW + colOff + n] = v;
            }
        }
    }
}

// ---------------------------------------------------------------------------
// 4) HMMA attention (portable mma.sync path — tcgen05 not assemblable here)
//    final[b,t,s] = sum_gh wp[t,gh] * relu( Q_gh[t,:].K_gh[s,:] )
//    CTA: 128(t) x 64(s); warp: 32x32; split-bf16: hh + hl + lh.
// ---------------------------------------------------------------------------
// smem layout (bytes); rows padded to 144B (72 bf16) for conflict-free ldmatrix
#define SM_QHI 0
#define SM_QLO 18432
#define SM_KHI 36864
#define SM_KLO 46080
#define SM_WP  55296
#define SM_TOTAL (SM_WP + 128 * NW * 4)   // 69632

__global__ void __launch_bounds__(256, 2)
attn_mma_kernel(float* __restrict__ out) {
    extern __shared__ char smem[];
    const uint32_t sb = smem_u32_of(smem);
    const int tid = threadIdx.x;
    const int wid = tid >> 5;
    const int lane = tid & 31;
    const int b = blockIdx.z;
    const int t0 = blockIdx.x * 128;
    const int s0 = blockIdx.y * 64;
    float* wp_s = (float*)(smem + SM_WP);

    // wp[t][gh] = probs[t, cfg] * Wproj[t, gh]
    for (int idx = tid; idx < 128 * NW; idx += 256) {
        int tt = idx / NW, gh = idx % NW;
        int cfg = (gh < 4) ? 0 : (gh < 12) ? 1 : 2;
        int row = b * TT + t0 + tt;
        wp_s[tt * NW + gh] = g_probs[row * 3 + cfg] * g_Wp[(size_t)row * NW + gh];
    }

    const int wm = wid & 3;    // m-tile (32 rows)
    const int wn = wid >> 2;   // n-tile (32 cols)

    float facc[2][4][4];
    #pragma unroll
    for (int mt = 0; mt < 2; mt++)
        #pragma unroll
        for (int nt = 0; nt < 4; nt++)
            #pragma unroll
            for (int j = 0; j < 4; j++) facc[mt][nt][j] = 0.f;

    // ldmatrix lane-address components
    const int arow = wm * 32 + (lane & 15);
    const int acol = (lane >> 4) << 3;                          // 0 or 8
    const int brow = wn * 32 + (lane & 7) + (((lane >> 4) & 1) << 3);
    const int bcol = ((lane >> 3) & 1) << 3;

    #pragma unroll 1
    for (int gh = 0; gh < NW; gh++) {
        int dh, qoff, koff;
        if (gh < 4)       { dh = 32;  qoff = gh * 32;               koff = 0;  }
        else if (gh < 12) { dh = 64;  qoff = 128 + (gh - 4) * 64;   koff = 32; }
        else              { dh = 128; qoff = 640 + (gh - 12) * 128; koff = 96; }
        const int nch = (dh > 64) ? 2 : 1;

        float dacc[2][4][4];
        #pragma unroll
        for (int mt = 0; mt < 2; mt++)
            #pragma unroll
            for (int nt = 0; nt < 4; nt++)
                #pragma unroll
                for (int j = 0; j < 4; j++) dacc[mt][nt][j] = 0.f;

        #pragma unroll 1
        for (int c = 0; c < nch; c++) {
            const int kb = c * 64;
            __syncthreads();   // previous chunk's MMAs done before overwrite

            {
                const size_t qbase = (size_t)(b * TT + t0) * NQ + qoff + kb;
                const size_t kbase = (size_t)(b * TT + s0) * NK + koff + kb;
                #pragma unroll
                for (int l = 0; l < 12; l++) {
                    int i = tid + l * 256;
                    if (i < 2048) {
                        int j = i & 1023;
                        int row = j >> 3, seg = j & 7;
                        const __nv_bfloat16* src = (i < 1024) ? g_Qhi : g_Qlo;
                        uint32_t sdst = sb + ((i < 1024) ? SM_QHI : SM_QLO) + row * 144 + seg * 16;
                        CPASYNC16(sdst, src + qbase + (size_t)row * NQ + seg * 8);
                    } else {
                        int j = i - 2048;
                        int lo = j >> 9; j &= 511;
                        int row = j >> 3, seg = j & 7;
                        int off = (lo ? SM_KLO : SM_KHI) + row * 144 + seg * 16;
                        if (kb + seg * 8 < dh) {
                            const __nv_bfloat16* src = lo ? g_Klo : g_Khi;
                            CPASYNC16(sb + off, src + kbase + (size_t)row * NK + seg * 8);
                        } else {
                            *(float4*)(smem + off) = make_float4(0.f, 0.f, 0.f, 0.f);
                        }
                    }
                }
            }
            CPCOMMIT();
            CPWAIT0();
            __syncthreads();

            #pragma unroll
            for (int kk = 0; kk < 4; kk++) {
                const int k16 = kk * 16;
                uint32_t ah[8], al[8], bv[8];
                uint32_t aaddr = sb + SM_QHI + arow * 144 + (k16 + acol) * 2;
                LDSM4(ah[0], ah[1], ah[2], ah[3], aaddr);
                LDSM4(ah[4], ah[5], ah[6], ah[7], aaddr + 16 * 144);
                uint32_t laddr = aaddr + (SM_QLO - SM_QHI);
                LDSM4(al[0], al[1], al[2], al[3], laddr);
                LDSM4(al[4], al[5], al[6], al[7], laddr + 16 * 144);
                uint32_t baddr = sb + SM_KHI + brow * 144 + (k16 + bcol) * 2;
                LDSM4(bv[0], bv[1], bv[2], bv[3], baddr);
                LDSM4(bv[4], bv[5], bv[6], bv[7], baddr + 16 * 144);
                #pragma unroll
                for (int mt = 0; mt < 2; mt++)
                    #pragma unroll
                    for (int nt = 0; nt < 4; nt++) {
                        MMA16816(dacc[mt][nt][0], dacc[mt][nt][1], dacc[mt][nt][2], dacc[mt][nt][3],
                                 ah[mt * 4 + 0], ah[mt * 4 + 1], ah[mt * 4 + 2], ah[mt * 4 + 3],
                                 bv[nt * 2 + 0], bv[nt * 2 + 1]);
                        MMA16816(dacc[mt][nt][0], dacc[mt][nt][1], dacc[mt][nt][2], dacc[mt][nt][3],
                                 al[mt * 4 + 0], al[mt * 4 + 1], al[mt * 4 + 2], al[mt * 4 + 3],
                                 bv[nt * 2 + 0], bv[nt * 2 + 1]);
                    }
                uint32_t bladdr = baddr + (SM_KLO - SM_KHI);
                LDSM4(bv[0], bv[1], bv[2], bv[3], bladdr);
                LDSM4(bv[4], bv[5], bv[6], bv[7], bladdr + 16 * 144);
                #pragma unroll
                for (int mt = 0; mt < 2; mt++)
                    #pragma unroll
                    for (int nt = 0; nt < 4; nt++)
                        MMA16816(dacc[mt][nt][0], dacc[mt][nt][1], dacc[mt][nt][2], dacc[mt][nt][3],
                                 ah[mt * 4 + 0], ah[mt * 4 + 1], ah[mt * 4 + 2], ah[mt * 4 + 3],
                                 bv[nt * 2 + 0], bv[nt * 2 + 1]);
            }
        }

        // epilogue: facc += wp * relu(dacc)
        #pragma unroll
        for (int mt = 0; mt < 2; mt++) {
            int r0 = wm * 32 + mt * 16 + (lane >> 2);
            float w0 = wp_s[r0 * NW + gh];
            float w1 = wp_s[(r0 + 8) * NW + gh];
            #pragma unroll
            for (int nt = 0; nt < 4; nt++) {
                facc[mt][nt][0] += w0 * fmaxf(dacc[mt][nt][0], 0.f);
                facc[mt][nt][1] += w0 * fmaxf(dacc[mt][nt][1], 0.f);
                facc[mt][nt][2] += w1 * fmaxf(dacc[mt][nt][2], 0.f);
                facc[mt][nt][3] += w1 * fmaxf(dacc[mt][nt][3], 0.f);
            }
        }
    }

    // store final tile
    #pragma unroll
    for (int mt = 0; mt < 2; mt++) {
        int row = t0 + wm * 32 + mt * 16 + (lane >> 2);
        #pragma unroll
        for (int nt = 0; nt < 4; nt++) {
            int col = s0 + wn * 32 + nt * 8 + (lane & 3) * 2;
            size_t o0 = (size_t)(b * TT + row) * TT + col;
            *(float2*)(out + o0) = make_float2(facc[mt][nt][0], facc[mt][nt][1]);
            *(float2*)(out + o0 + 8 * TT) = make_float2(facc[mt][nt][2], facc[mt][nt][3]);
        }
    }
}

// ---------------------------------------------------------------------------
extern "C" void kernel_launch(void* const* d_in, const int* in_sizes, int n_in,
                              void* d_out, int out_size) {
    const float* x   = (const float*)d_in[0];
    const float* w1  = (const float*)d_in[1];
    const float* b1  = (const float*)d_in[2];
    const float* w2  = (const float*)d_in[3];
    const float* b2  = (const float*)d_in[4];
    const float* w3  = (const float*)d_in[5];
    const float* b3  = (const float*)d_in[6];
    const float* qw0 = (const float*)d_in[7];
    const float* kw0 = (const float*)d_in[8];
    const float* ww0 = (const float*)d_in[9];
    const float* qw1 = (const float*)d_in[10];
    const float* kw1 = (const float*)d_in[11];
    const float* ww1 = (const float*)d_in[12];
    const float* qw2 = (const float*)d_in[13];
    const float* kw2 = (const float*)d_in[14];
    const float* ww2 = (const float*)d_in[15];
    float* out = (float*)d_out;

    stats_kernel<<<dim3(DM / 256, BB), 256>>>(x);
    selector_kernel<<<BB * TT, 256>>>(x, w1, b1, w2, b2, w3, b3);

    // Q projections -> bf16 hi/lo (ld = 2688), column offsets 0 / 128 / 640
    proj_gemm<<<dim3(64, 2), 256>>>(x, qw0, 128, 0, NQ, 0);
    proj_gemm<<<dim3(64, 8), 256>>>(x, qw1, 512, 0, NQ, 128);
    proj_gemm<<<dim3(64, 32), 256>>>(x, qw2, 2048, 0, NQ, 640);
    // K projections -> bf16 hi/lo (ld = 224), offsets 0 / 32 / 96
    proj_gemm<<<dim3(64, 1), 256>>>(x, kw0, 32, 1, NK, 0);
    proj_gemm<<<dim3(64, 1), 256>>>(x, kw1, 64, 1, NK, 32);
    proj_gemm<<<dim3(64, 2), 256>>>(x, kw2, 128, 1, NK, 96);
    // W projections -> fp32 (ld = 28), offsets 0 / 4 / 12
    proj_gemm<<<dim3(64, 1), 256>>>(x, ww0, 4, 2, NW, 0);
    proj_gemm<<<dim3(64, 1), 256>>>(x, ww1, 8, 2, NW, 4);
    proj_gemm<<<dim3(64, 1), 256>>>(x, ww2, 16, 2, NW, 12);

    cudaFuncSetAttribute(attn_mma_kernel, cudaFuncAttributeMaxDynamicSharedMemorySize, SM_TOTAL);
    attn_mma_kernel<<<dim3(TT / 128, TT / 64, BB), 256, SM_TOTAL>>>(out);
}

// round 7
// speedup vs baseline: 2.7631x; 1.7738x over previous
#include <cuda_runtime.h>
#include <cuda_bf16.h>
#include <math.h>
#include <stdint.h>

#define BB 2
#define TT 2048
#define DM 1024
#define NQ 2688   // 4*32 + 8*64 + 16*128
#define NK 224    // 32 + 64 + 128
#define NW 28     // 4 + 8 + 16
#define NALL 2940 // NQ + NK + NW

// ---------------- device scratch (no allocation allowed) --------------------
__device__ float g_mean[BB * DM];
__device__ float g_std[BB * DM];
__device__ float g_probs[BB * TT * 3];
__device__ float g_Wp[(size_t)BB * TT * NW];
__device__ __align__(256) __nv_bfloat16 g_Qhi[(size_t)BB * TT * NQ];
__device__ __align__(256) __nv_bfloat16 g_Qlo[(size_t)BB * TT * NQ];
__device__ __align__(256) __nv_bfloat16 g_Khi[(size_t)BB * TT * NK];
__device__ __align__(256) __nv_bfloat16 g_Klo[(size_t)BB * TT * NK];
__device__ __align__(256) __nv_bfloat16 g_Xhi[(size_t)BB * TT * DM];
__device__ __align__(256) __nv_bfloat16 g_Xlo[(size_t)BB * TT * DM];
__device__ __align__(256) __nv_bfloat16 g_Whi[(size_t)NALL * DM];
__device__ __align__(256) __nv_bfloat16 g_Wlo[(size_t)NALL * DM];

// ---------------- portable PTX helpers (no sm_103a-only instructions) -------
__device__ __forceinline__ uint32_t smem_u32_of(const void* p) {
    uint32_t a;
    asm("{ .reg .u64 t; cvta.to.shared.u64 t, %1; cvt.u32.u64 %0, t; }" : "=r"(a) : "l"(p));
    return a;
}
#define CPASYNC16(s, g) \
    asm volatile("cp.async.cg.shared.global [%0], [%1], 16;" :: "r"(s), "l"(g))
#define CPCOMMIT() asm volatile("cp.async.commit_group;" ::: "memory")
#define CPWAIT0()  asm volatile("cp.async.wait_group 0;" ::: "memory")
#define LDSM4(r0, r1, r2, r3, addr) \
    asm volatile("ldmatrix.sync.aligned.m8n8.x4.shared.b16 {%0,%1,%2,%3}, [%4];" \
                 : "=r"(r0), "=r"(r1), "=r"(r2), "=r"(r3) : "r"(addr))
#define MMA16816(d0, d1, d2, d3, a0, a1, a2, a3, b0, b1) \
    asm volatile("mma.sync.aligned.m16n8k16.row.col.f32.bf16.bf16.f32 " \
                 "{%0,%1,%2,%3}, {%4,%5,%6,%7}, {%8,%9}, {%0,%1,%2,%3};" \
                 : "+f"(d0), "+f"(d1), "+f"(d2), "+f"(d3) \
                 : "r"(a0), "r"(a1), "r"(a2), "r"(a3), "r"(b0), "r"(b1))

// ---------------------------------------------------------------------------
// 1) per-(b,d) mean / unbiased std over T
// ---------------------------------------------------------------------------
__global__ void stats_kernel(const float* __restrict__ x) {
    int d = blockIdx.x * blockDim.x + threadIdx.x;
    int b = blockIdx.y;
    const float* px = x + (size_t)b * TT * DM + d;
    double s = 0.0, s2 = 0.0;
    for (int t = 0; t < TT; t++) {
        double v = (double)px[(size_t)t * DM];
        s += v; s2 += v * v;
    }
    double m = s / (double)TT;
    double var = (s2 - s * s / (double)TT) / (double)(TT - 1);
    if (var < 0.0) var = 0.0;
    g_mean[b * DM + d] = (float)m;
    g_std[b * DM + d] = (float)sqrt(var);
}

// ---------------------------------------------------------------------------
// 2) selector MLP + softmax
// ---------------------------------------------------------------------------
__global__ void selector_kernel(const float* __restrict__ x,
                                const float* __restrict__ w1, const float* __restrict__ b1,
                                const float* __restrict__ w2, const float* __restrict__ b2,
                                const float* __restrict__ w3, const float* __restrict__ b3) {
    __shared__ float feats[DM];
    __shared__ float h1[64];
    __shared__ float h2[64];
    __shared__ float lg[3];
    int row = blockIdx.x;
    int b = row / TT;
    int t = row % TT;
    int tid = threadIdx.x;
    float posv = 0.1f * ((float)t / (float)TT);

    for (int i = tid; i < DM; i += 256)
        feats[i] = x[(size_t)row * DM + i] + g_mean[b * DM + i] + g_std[b * DM + i] + posv;
    __syncthreads();

    int warp = tid >> 5, lane = tid & 31;
    for (int j = warp; j < 64; j += 8) {
        const float* wr = w1 + j * DM;
        float a = 0.f;
        for (int i = lane; i < DM; i += 32) a += feats[i] * wr[i];
        #pragma unroll
        for (int o = 16; o; o >>= 1) a += __shfl_down_sync(0xffffffffu, a, o);
        if (lane == 0) h1[j] = fmaxf(a + b1[j], 0.f);
    }
    __syncthreads();
    for (int j = warp; j < 64; j += 8) {
        const float* wr = w2 + j * 64;
        float a = h1[lane] * wr[lane] + h1[lane + 32] * wr[lane + 32];
        #pragma unroll
        for (int o = 16; o; o >>= 1) a += __shfl_down_sync(0xffffffffu, a, o);
        if (lane == 0) h2[j] = fmaxf(a + b2[j], 0.f);
    }
    __syncthreads();
    if (tid < 3) {
        float a = b3[tid];
        #pragma unroll 8
        for (int i = 0; i < 64; i++) a += h2[i] * w3[tid * 64 + i];
        lg[tid] = a;
    }
    __syncthreads();
    if (tid == 0) {
        float m = fmaxf(lg[0], fmaxf(lg[1], lg[2]));
        float e0 = expf(lg[0] - m), e1 = expf(lg[1] - m), e2 = expf(lg[2] - m);
        float inv = 1.f / (e0 + e1 + e2);
        g_probs[row * 3 + 0] = e0 * inv;
        g_probs[row * 3 + 1] = e1 * inv;
        g_probs[row * 3 + 2] = e2 * inv;
    }
}

// ---------------------------------------------------------------------------
// 3a) split fp32 -> bf16 hi/lo. Destination selected BY FLAG inside the
//     kernel (device globals must not be passed as host-side args).
//     whichDst: 0 -> g_Xhi/g_Xlo, 1 -> g_Whi/g_Wlo. rowOff in rows.
// ---------------------------------------------------------------------------
__global__ void split_kernel(const float* __restrict__ src, int whichDst, int rowOff) {
    __nv_bfloat16* dhi = whichDst ? g_Whi : g_Xhi;
    __nv_bfloat16* dlo = whichDst ? g_Wlo : g_Xlo;
    int row = blockIdx.x + rowOff;
    int c = threadIdx.x * 4;
    float4 v = *(const float4*)(src + (size_t)blockIdx.x * DM + c);
    __nv_bfloat16 h0 = __float2bfloat16(v.x), h1 = __float2bfloat16(v.y);
    __nv_bfloat16 h2 = __float2bfloat16(v.z), h3 = __float2bfloat16(v.w);
    __nv_bfloat162* ph = (__nv_bfloat162*)(dhi + (size_t)row * DM + c);
    __nv_bfloat162* pl = (__nv_bfloat162*)(dlo + (size_t)row * DM + c);
    ph[0] = __nv_bfloat162(h0, h1);
    ph[1] = __nv_bfloat162(h2, h3);
    pl[0] = __nv_bfloat162(__float2bfloat16(v.x - __bfloat162float(h0)),
                           __float2bfloat16(v.y - __bfloat162float(h1)));
    pl[1] = __nv_bfloat162(__float2bfloat16(v.z - __bfloat162float(h2)),
                           __float2bfloat16(v.w - __bfloat162float(h3)));
}

// ---------------------------------------------------------------------------
// 3b) HMMA projection GEMM: C[4096, 2940] = X @ W^T (split-bf16 3-term)
//     epilogue routes cols: [0,2688) -> Q hi/lo, [2688,2912) -> K hi/lo,
//     [2912,2940) -> Wp fp32.
// ---------------------------------------------------------------------------
#define PJ_AHI 0
#define PJ_ALO 18432
#define PJ_BHI 36864
#define PJ_BLO 46080
#define PJ_TOTAL 55296

__global__ void __launch_bounds__(256, 2)
proj_mma_kernel() {
    extern __shared__ char smem[];
    const uint32_t sb = smem_u32_of(smem);
    const int tid = threadIdx.x;
    const int wid = tid >> 5;
    const int lane = tid & 31;
    const int m0 = blockIdx.x * 128;
    const int n0 = blockIdx.y * 64;

    const int wm = wid & 3;
    const int wn = wid >> 2;

    float facc[2][4][4];
    #pragma unroll
    for (int mt = 0; mt < 2; mt++)
        #pragma unroll
        for (int nt = 0; nt < 4; nt++)
            #pragma unroll
            for (int j = 0; j < 4; j++) facc[mt][nt][j] = 0.f;

    const int arow = wm * 32 + (lane & 15);
    const int acol = (lane >> 4) << 3;
    const int brow = wn * 32 + (lane & 7) + (((lane >> 4) & 1) << 3);
    const int bcol = ((lane >> 3) & 1) << 3;

    #pragma unroll 1
    for (int c = 0; c < DM / 64; c++) {
        const int k0 = c * 64;
        __syncthreads();
        {
            #pragma unroll
            for (int l = 0; l < 12; l++) {
                int i = tid + l * 256;
                if (i < 2048) {
                    int j = i & 1023;
                    int row = j >> 3, seg = j & 7;
                    const __nv_bfloat16* src = (i < 1024) ? g_Xhi : g_Xlo;
                    uint32_t sdst = sb + ((i < 1024) ? PJ_AHI : PJ_ALO) + row * 144 + seg * 16;
                    CPASYNC16(sdst, src + (size_t)(m0 + row) * DM + k0 + seg * 8);
                } else {
                    int j = i - 2048;
                    int lo = j >> 9; j &= 511;
                    int row = j >> 3, seg = j & 7;
                    int off = (lo ? PJ_BLO : PJ_BHI) + row * 144 + seg * 16;
                    if (n0 + row < NALL) {
                        const __nv_bfloat16* src = lo ? g_Wlo : g_Whi;
                        CPASYNC16(sb + off, src + (size_t)(n0 + row) * DM + k0 + seg * 8);
                    } else {
                        *(float4*)(smem + off) = make_float4(0.f, 0.f, 0.f, 0.f);
                    }
                }
            }
        }
        CPCOMMIT();
        CPWAIT0();
        __syncthreads();

        #pragma unroll
        for (int kk = 0; kk < 4; kk++) {
            const int k16 = kk * 16;
            uint32_t ah[8], al[8], bv[8];
            uint32_t aaddr = sb + PJ_AHI + arow * 144 + (k16 + acol) * 2;
            LDSM4(ah[0], ah[1], ah[2], ah[3], aaddr);
            LDSM4(ah[4], ah[5], ah[6], ah[7], aaddr + 16 * 144);
            uint32_t laddr = aaddr + (PJ_ALO - PJ_AHI);
            LDSM4(al[0], al[1], al[2], al[3], laddr);
            LDSM4(al[4], al[5], al[6], al[7], laddr + 16 * 144);
            uint32_t baddr = sb + PJ_BHI + brow * 144 + (k16 + bcol) * 2;
            LDSM4(bv[0], bv[1], bv[2], bv[3], baddr);
            LDSM4(bv[4], bv[5], bv[6], bv[7], baddr + 16 * 144);
            #pragma unroll
            for (int mt = 0; mt < 2; mt++)
                #pragma unroll
                for (int nt = 0; nt < 4; nt++) {
                    MMA16816(facc[mt][nt][0], facc[mt][nt][1], facc[mt][nt][2], facc[mt][nt][3],
                             ah[mt * 4 + 0], ah[mt * 4 + 1], ah[mt * 4 + 2], ah[mt * 4 + 3],
                             bv[nt * 2 + 0], bv[nt * 2 + 1]);
                    MMA16816(facc[mt][nt][0], facc[mt][nt][1], facc[mt][nt][2], facc[mt][nt][3],
                             al[mt * 4 + 0], al[mt * 4 + 1], al[mt * 4 + 2], al[mt * 4 + 3],
                             bv[nt * 2 + 0], bv[nt * 2 + 1]);
                }
            uint32_t bladdr = baddr + (PJ_BLO - PJ_BHI);
            LDSM4(bv[0], bv[1], bv[2], bv[3], bladdr);
            LDSM4(bv[4], bv[5], bv[6], bv[7], bladdr + 16 * 144);
            #pragma unroll
            for (int mt = 0; mt < 2; mt++)
                #pragma unroll
                for (int nt = 0; nt < 4; nt++)
                    MMA16816(facc[mt][nt][0], facc[mt][nt][1], facc[mt][nt][2], facc[mt][nt][3],
                             ah[mt * 4 + 0], ah[mt * 4 + 1], ah[mt * 4 + 2], ah[mt * 4 + 3],
                             bv[nt * 2 + 0], bv[nt * 2 + 1]);
        }
    }

    // epilogue: route column pairs to Q (bf16 hi/lo) / K (bf16 hi/lo) / Wp (f32)
    #pragma unroll
    for (int mt = 0; mt < 2; mt++) {
        #pragma unroll
        for (int half = 0; half < 2; half++) {
            int m = m0 + wm * 32 + mt * 16 + (lane >> 2) + half * 8;
            #pragma unroll
            for (int nt = 0; nt < 4; nt++) {
                int col = n0 + wn * 32 + nt * 8 + (lane & 3) * 2;
                float v0 = facc[mt][nt][half * 2 + 0];
                float v1 = facc[mt][nt][half * 2 + 1];
                if (col < NQ) {
                    __nv_bfloat16 h0 = __float2bfloat16(v0), h1 = __float2bfloat16(v1);
                    size_t o = (size_t)m * NQ + col;
                    *(__nv_bfloat162*)(g_Qhi + o) = __nv_bfloat162(h0, h1);
                    *(__nv_bfloat162*)(g_Qlo + o) =
                        __nv_bfloat162(__float2bfloat16(v0 - __bfloat162float(h0)),
                                       __float2bfloat16(v1 - __bfloat162float(h1)));
                } else if (col < NQ + NK) {
                    __nv_bfloat16 h0 = __float2bfloat16(v0), h1 = __float2bfloat16(v1);
                    size_t o = (size_t)m * NK + (col - NQ);
                    *(__nv_bfloat162*)(g_Khi + o) = __nv_bfloat162(h0, h1);
                    *(__nv_bfloat162*)(g_Klo + o) =
                        __nv_bfloat162(__float2bfloat16(v0 - __bfloat162float(h0)),
                                       __float2bfloat16(v1 - __bfloat162float(h1)));
                } else if (col < NALL) {
                    *(float2*)(g_Wp + (size_t)m * NW + (col - NQ - NK)) = make_float2(v0, v1);
                }
            }
        }
    }
}

// ---------------------------------------------------------------------------
// 4) HMMA attention
//    final[b,t,s] = sum_gh wp[t,gh] * relu( Q_gh[t,:].K_gh[s,:] )
//    CTA: 128(t) x 64(s); warp: 32x32; split-bf16: hh + hl + lh.
// ---------------------------------------------------------------------------
#define SM_QHI 0
#define SM_QLO 18432
#define SM_KHI 36864
#define SM_KLO 46080
#define SM_WP  55296
#define SM_TOTAL (SM_WP + 128 * NW * 4)   // 69632

__global__ void __launch_bounds__(256, 2)
attn_mma_kernel(float* __restrict__ out) {
    extern __shared__ char smem[];
    const uint32_t sb = smem_u32_of(smem);
    const int tid = threadIdx.x;
    const int wid = tid >> 5;
    const int lane = tid & 31;
    const int b = blockIdx.z;
    const int t0 = blockIdx.x * 128;
    const int s0 = blockIdx.y * 64;
    float* wp_s = (float*)(smem + SM_WP);

    for (int idx = tid; idx < 128 * NW; idx += 256) {
        int tt = idx / NW, gh = idx % NW;
        int cfg = (gh < 4) ? 0 : (gh < 12) ? 1 : 2;
        int row = b * TT + t0 + tt;
        wp_s[tt * NW + gh] = g_probs[row * 3 + cfg] * g_Wp[(size_t)row * NW + gh];
    }

    const int wm = wid & 3;
    const int wn = wid >> 2;

    float facc[2][4][4];
    #pragma unroll
    for (int mt = 0; mt < 2; mt++)
        #pragma unroll
        for (int nt = 0; nt < 4; nt++)
            #pragma unroll
            for (int j = 0; j < 4; j++) facc[mt][nt][j] = 0.f;

    const int arow = wm * 32 + (lane & 15);
    const int acol = (lane >> 4) << 3;
    const int brow = wn * 32 + (lane & 7) + (((lane >> 4) & 1) << 3);
    const int bcol = ((lane >> 3) & 1) << 3;

    #pragma unroll 1
    for (int gh = 0; gh < NW; gh++) {
        int dh, qoff, koff;
        if (gh < 4)       { dh = 32;  qoff = gh * 32;               koff = 0;  }
        else if (gh < 12) { dh = 64;  qoff = 128 + (gh - 4) * 64;   koff = 32; }
        else              { dh = 128; qoff = 640 + (gh - 12) * 128; koff = 96; }
        const int nch = (dh > 64) ? 2 : 1;

        float dacc[2][4][4];
        #pragma unroll
        for (int mt = 0; mt < 2; mt++)
            #pragma unroll
            for (int nt = 0; nt < 4; nt++)
                #pragma unroll
                for (int j = 0; j < 4; j++) dacc[mt][nt][j] = 0.f;

        #pragma unroll 1
        for (int c = 0; c < nch; c++) {
            const int kb = c * 64;
            __syncthreads();

            {
                const size_t qbase = (size_t)(b * TT + t0) * NQ + qoff + kb;
                const size_t kbase = (size_t)(b * TT + s0) * NK + koff + kb;
                #pragma unroll
                for (int l = 0; l < 12; l++) {
                    int i = tid + l * 256;
                    if (i < 2048) {
                        int j = i & 1023;
                        int row = j >> 3, seg = j & 7;
                        const __nv_bfloat16* src = (i < 1024) ? g_Qhi : g_Qlo;
                        uint32_t sdst = sb + ((i < 1024) ? SM_QHI : SM_QLO) + row * 144 + seg * 16;
                        CPASYNC16(sdst, src + qbase + (size_t)row * NQ + seg * 8);
                    } else {
                        int j = i - 2048;
                        int lo = j >> 9; j &= 511;
                        int row = j >> 3, seg = j & 7;
                        int off = (lo ? SM_KLO : SM_KHI) + row * 144 + seg * 16;
                        if (kb + seg * 8 < dh) {
                            const __nv_bfloat16* src = lo ? g_Klo : g_Khi;
                            CPASYNC16(sb + off, src + kbase + (size_t)row * NK + seg * 8);
                        } else {
                            *(float4*)(smem + off) = make_float4(0.f, 0.f, 0.f, 0.f);
                        }
                    }
                }
            }
            CPCOMMIT();
            CPWAIT0();
            __syncthreads();

            #pragma unroll
            for (int kk = 0; kk < 4; kk++) {
                const int k16 = kk * 16;
                uint32_t ah[8], al[8], bv[8];
                uint32_t aaddr = sb + SM_QHI + arow * 144 + (k16 + acol) * 2;
                LDSM4(ah[0], ah[1], ah[2], ah[3], aaddr);
                LDSM4(ah[4], ah[5], ah[6], ah[7], aaddr + 16 * 144);
                uint32_t laddr = aaddr + (SM_QLO - SM_QHI);
                LDSM4(al[0], al[1], al[2], al[3], laddr);
                LDSM4(al[4], al[5], al[6], al[7], laddr + 16 * 144);
                uint32_t baddr = sb + SM_KHI + brow * 144 + (k16 + bcol) * 2;
                LDSM4(bv[0], bv[1], bv[2], bv[3], baddr);
                LDSM4(bv[4], bv[5], bv[6], bv[7], baddr + 16 * 144);
                #pragma unroll
                for (int mt = 0; mt < 2; mt++)
                    #pragma unroll
                    for (int nt = 0; nt < 4; nt++) {
                        MMA16816(dacc[mt][nt][0], dacc[mt][nt][1], dacc[mt][nt][2], dacc[mt][nt][3],
                                 ah[mt * 4 + 0], ah[mt * 4 + 1], ah[mt * 4 + 2], ah[mt * 4 + 3],
                                 bv[nt * 2 + 0], bv[nt * 2 + 1]);
                        MMA16816(dacc[mt][nt][0], dacc[mt][nt][1], dacc[mt][nt][2], dacc[mt][nt][3],
                                 al[mt * 4 + 0], al[mt * 4 + 1], al[mt * 4 + 2], al[mt * 4 + 3],
                                 bv[nt * 2 + 0], bv[nt * 2 + 1]);
                    }
                uint32_t bladdr = baddr + (SM_KLO - SM_KHI);
                LDSM4(bv[0], bv[1], bv[2], bv[3], bladdr);
                LDSM4(bv[4], bv[5], bv[6], bv[7], bladdr + 16 * 144);
                #pragma unroll
                for (int mt = 0; mt < 2; mt++)
                    #pragma unroll
                    for (int nt = 0; nt < 4; nt++)
                        MMA16816(dacc[mt][nt][0], dacc[mt][nt][1], dacc[mt][nt][2], dacc[mt][nt][3],
                                 ah[mt * 4 + 0], ah[mt * 4 + 1], ah[mt * 4 + 2], ah[mt * 4 + 3],
                                 bv[nt * 2 + 0], bv[nt * 2 + 1]);
            }
        }

        #pragma unroll
        for (int mt = 0; mt < 2; mt++) {
            int r0 = wm * 32 + mt * 16 + (lane >> 2);
            float w0 = wp_s[r0 * NW + gh];
            float w1 = wp_s[(r0 + 8) * NW + gh];
            #pragma unroll
            for (int nt = 0; nt < 4; nt++) {
                facc[mt][nt][0] += w0 * fmaxf(dacc[mt][nt][0], 0.f);
                facc[mt][nt][1] += w0 * fmaxf(dacc[mt][nt][1], 0.f);
                facc[mt][nt][2] += w1 * fmaxf(dacc[mt][nt][2], 0.f);
                facc[mt][nt][3] += w1 * fmaxf(dacc[mt][nt][3], 0.f);
            }
        }
    }

    #pragma unroll
    for (int mt = 0; mt < 2; mt++) {
        int row = t0 + wm * 32 + mt * 16 + (lane >> 2);
        #pragma unroll
        for (int nt = 0; nt < 4; nt++) {
            int col = s0 + wn * 32 + nt * 8 + (lane & 3) * 2;
            size_t o0 = (size_t)(b * TT + row) * TT + col;
            *(float2*)(out + o0) = make_float2(facc[mt][nt][0], facc[mt][nt][1]);
            *(float2*)(out + o0 + 8 * TT) = make_float2(facc[mt][nt][2], facc[mt][nt][3]);
        }
    }
}

// ---------------------------------------------------------------------------
extern "C" void kernel_launch(void* const* d_in, const int* in_sizes, int n_in,
                              void* d_out, int out_size) {
    const float* x   = (const float*)d_in[0];
    const float* w1  = (const float*)d_in[1];
    const float* b1  = (const float*)d_in[2];
    const float* w2  = (const float*)d_in[3];
    const float* b2  = (const float*)d_in[4];
    const float* w3  = (const float*)d_in[5];
    const float* b3  = (const float*)d_in[6];
    const float* qw0 = (const float*)d_in[7];
    const float* kw0 = (const float*)d_in[8];
    const float* ww0 = (const float*)d_in[9];
    const float* qw1 = (const float*)d_in[10];
    const float* kw1 = (const float*)d_in[11];
    const float* ww1 = (const float*)d_in[12];
    const float* qw2 = (const float*)d_in[13];
    const float* kw2 = (const float*)d_in[14];
    const float* ww2 = (const float*)d_in[15];
    float* out = (float*)d_out;

    stats_kernel<<<dim3(DM / 256, BB), 256>>>(x);
    selector_kernel<<<BB * TT, 256>>>(x, w1, b1, w2, b2, w3, b3);

    // splits: X -> Xhi/Xlo (whichDst=0); weights row-concat into Whi/Wlo (=1)
    split_kernel<<<BB * TT, 256>>>(x,   0, 0);
    split_kernel<<<128,  256>>>(qw0, 1, 0);
    split_kernel<<<512,  256>>>(qw1, 1, 128);
    split_kernel<<<2048, 256>>>(qw2, 1, 640);
    split_kernel<<<32,   256>>>(kw0, 1, 2688);
    split_kernel<<<64,   256>>>(kw1, 1, 2720);
    split_kernel<<<128,  256>>>(kw2, 1, 2784);
    split_kernel<<<4,    256>>>(ww0, 1, 2912);
    split_kernel<<<8,    256>>>(ww1, 1, 2916);
    split_kernel<<<16,   256>>>(ww2, 1, 2924);

    // fused HMMA projection GEMM
    cudaFuncSetAttribute(proj_mma_kernel, cudaFuncAttributeMaxDynamicSharedMemorySize, PJ_TOTAL);
    proj_mma_kernel<<<dim3(BB * TT / 128, (NALL + 63) / 64), 256, PJ_TOTAL>>>();

    cudaFuncSetAttribute(attn_mma_kernel, cudaFuncAttributeMaxDynamicSharedMemorySize, SM_TOTAL);
    attn_mma_kernel<<<dim3(TT / 128, TT / 64, BB), 256, SM_TOTAL>>>(out);
}

// round 8
// speedup vs baseline: 2.8475x; 1.0305x over previous
#include <cuda_runtime.h>
#include <cuda_bf16.h>
#include <math.h>
#include <stdint.h>

#define BB 2
#define TT 2048
#define DM 1024
#define NQ 2688   // 4*32 + 8*64 + 16*128
#define NK 224    // 32 + 64 + 128
#define NW 28     // 4 + 8 + 16
#define NALL 2940 // NQ + NK + NW

// ---------------- device scratch (no allocation allowed) --------------------
__device__ float g_mean[BB * DM];
__device__ float g_std[BB * DM];
__device__ float g_probs[BB * TT * 3];
__device__ float g_Wp[(size_t)BB * TT * NW];
__device__ __align__(256) __nv_bfloat16 g_Qhi[(size_t)BB * TT * NQ];
__device__ __align__(256) __nv_bfloat16 g_Qlo[(size_t)BB * TT * NQ];
__device__ __align__(256) __nv_bfloat16 g_Khi[(size_t)BB * TT * NK];
__device__ __align__(256) __nv_bfloat16 g_Klo[(size_t)BB * TT * NK];
__device__ __align__(256) __nv_bfloat16 g_Xhi[(size_t)BB * TT * DM];
__device__ __align__(256) __nv_bfloat16 g_Xlo[(size_t)BB * TT * DM];
__device__ __align__(256) __nv_bfloat16 g_Whi[(size_t)NALL * DM];
__device__ __align__(256) __nv_bfloat16 g_Wlo[(size_t)NALL * DM];

// ---------------- portable PTX helpers --------------------------------------
__device__ __forceinline__ uint32_t smem_u32_of(const void* p) {
    uint32_t a;
    asm("{ .reg .u64 t; cvta.to.shared.u64 t, %1; cvt.u32.u64 %0, t; }" : "=r"(a) : "l"(p));
    return a;
}
#define CPASYNC16(s, g) \
    asm volatile("cp.async.cg.shared.global [%0], [%1], 16;" :: "r"(s), "l"(g))
#define CPCOMMIT() asm volatile("cp.async.commit_group;" ::: "memory")
#define CPWAIT0()  asm volatile("cp.async.wait_group 0;" ::: "memory")
#define LDSM4(r0, r1, r2, r3, addr) \
    asm volatile("ldmatrix.sync.aligned.m8n8.x4.shared.b16 {%0,%1,%2,%3}, [%4];" \
                 : "=r"(r0), "=r"(r1), "=r"(r2), "=r"(r3) : "r"(addr))
#define MMA16816(d0, d1, d2, d3, a0, a1, a2, a3, b0, b1) \
    asm volatile("mma.sync.aligned.m16n8k16.row.col.f32.bf16.bf16.f32 " \
                 "{%0,%1,%2,%3}, {%4,%5,%6,%7}, {%8,%9}, {%0,%1,%2,%3};" \
                 : "+f"(d0), "+f"(d1), "+f"(d2), "+f"(d3) \
                 : "r"(a0), "r"(a1), "r"(a2), "r"(a3), "r"(b0), "r"(b1))

// ---------------------------------------------------------------------------
// 1) per-(b,d) mean / unbiased std over T
// ---------------------------------------------------------------------------
__global__ void stats_kernel(const float* __restrict__ x) {
    int d = blockIdx.x * blockDim.x + threadIdx.x;
    int b = blockIdx.y;
    const float* px = x + (size_t)b * TT * DM + d;
    double s = 0.0, s2 = 0.0;
    for (int t = 0; t < TT; t++) {
        double v = (double)px[(size_t)t * DM];
        s += v; s2 += v * v;
    }
    double m = s / (double)TT;
    double var = (s2 - s * s / (double)TT) / (double)(TT - 1);
    if (var < 0.0) var = 0.0;
    g_mean[b * DM + d] = (float)m;
    g_std[b * DM + d] = (float)sqrt(var);
}

// ---------------------------------------------------------------------------
// 2) selector MLP + softmax
// ---------------------------------------------------------------------------
__global__ void selector_kernel(const float* __restrict__ x,
                                const float* __restrict__ w1, const float* __restrict__ b1,
                                const float* __restrict__ w2, const float* __restrict__ b2,
                                const float* __restrict__ w3, const float* __restrict__ b3) {
    __shared__ float feats[DM];
    __shared__ float h1[64];
    __shared__ float h2[64];
    __shared__ float lg[3];
    int row = blockIdx.x;
    int b = row / TT;
    int t = row % TT;
    int tid = threadIdx.x;
    float posv = 0.1f * ((float)t / (float)TT);

    for (int i = tid; i < DM; i += 256)
        feats[i] = x[(size_t)row * DM + i] + g_mean[b * DM + i] + g_std[b * DM + i] + posv;
    __syncthreads();

    int warp = tid >> 5, lane = tid & 31;
    for (int j = warp; j < 64; j += 8) {
        const float* wr = w1 + j * DM;
        float a = 0.f;
        for (int i = lane; i < DM; i += 32) a += feats[i] * wr[i];
        #pragma unroll
        for (int o = 16; o; o >>= 1) a += __shfl_down_sync(0xffffffffu, a, o);
        if (lane == 0) h1[j] = fmaxf(a + b1[j], 0.f);
    }
    __syncthreads();
    for (int j = warp; j < 64; j += 8) {
        const float* wr = w2 + j * 64;
        float a = h1[lane] * wr[lane] + h1[lane + 32] * wr[lane + 32];
        #pragma unroll
        for (int o = 16; o; o >>= 1) a += __shfl_down_sync(0xffffffffu, a, o);
        if (lane == 0) h2[j] = fmaxf(a + b2[j], 0.f);
    }
    __syncthreads();
    if (tid < 3) {
        float a = b3[tid];
        #pragma unroll 8
        for (int i = 0; i < 64; i++) a += h2[i] * w3[tid * 64 + i];
        lg[tid] = a;
    }
    __syncthreads();
    if (tid == 0) {
        float m = fmaxf(lg[0], fmaxf(lg[1], lg[2]));
        float e0 = expf(lg[0] - m), e1 = expf(lg[1] - m), e2 = expf(lg[2] - m);
        float inv = 1.f / (e0 + e1 + e2);
        g_probs[row * 3 + 0] = e0 * inv;
        g_probs[row * 3 + 1] = e1 * inv;
        g_probs[row * 3 + 2] = e2 * inv;
    }
}

// ---------------------------------------------------------------------------
// 3a) split fp32 -> bf16 hi/lo (destination picked by flag inside kernel)
// ---------------------------------------------------------------------------
__global__ void split_kernel(const float* __restrict__ src, int whichDst, int rowOff) {
    __nv_bfloat16* dhi = whichDst ? g_Whi : g_Xhi;
    __nv_bfloat16* dlo = whichDst ? g_Wlo : g_Xlo;
    int row = blockIdx.x + rowOff;
    int c = threadIdx.x * 4;
    float4 v = *(const float4*)(src + (size_t)blockIdx.x * DM + c);
    __nv_bfloat16 h0 = __float2bfloat16(v.x), h1 = __float2bfloat16(v.y);
    __nv_bfloat16 h2 = __float2bfloat16(v.z), h3 = __float2bfloat16(v.w);
    __nv_bfloat162* ph = (__nv_bfloat162*)(dhi + (size_t)row * DM + c);
    __nv_bfloat162* pl = (__nv_bfloat162*)(dlo + (size_t)row * DM + c);
    ph[0] = __nv_bfloat162(h0, h1);
    ph[1] = __nv_bfloat162(h2, h3);
    pl[0] = __nv_bfloat162(__float2bfloat16(v.x - __bfloat162float(h0)),
                           __float2bfloat16(v.y - __bfloat162float(h1)));
    pl[1] = __nv_bfloat162(__float2bfloat16(v.z - __bfloat162float(h2)),
                           __float2bfloat16(v.w - __bfloat162float(h3)));
}

// ---------------------------------------------------------------------------
// 3b) HMMA projection GEMM: C[4096, 2940] = X @ W^T (split-bf16 3-term)
// ---------------------------------------------------------------------------
#define PJ_AHI 0
#define PJ_ALO 18432
#define PJ_BHI 36864
#define PJ_BLO 46080
#define PJ_TOTAL 55296

__global__ void __launch_bounds__(256, 2)
proj_mma_kernel() {
    extern __shared__ char smem[];
    const uint32_t sb = smem_u32_of(smem);
    const int tid = threadIdx.x;
    const int wid = tid >> 5;
    const int lane = tid & 31;
    const int m0 = blockIdx.x * 128;
    const int n0 = blockIdx.y * 64;

    const int wm = wid & 3;
    const int wn = wid >> 2;

    float facc[2][4][4];
    #pragma unroll
    for (int mt = 0; mt < 2; mt++)
        #pragma unroll
        for (int nt = 0; nt < 4; nt++)
            #pragma unroll
            for (int j = 0; j < 4; j++) facc[mt][nt][j] = 0.f;

    const int arow = wm * 32 + (lane & 15);
    const int acol = (lane >> 4) << 3;
    const int brow = wn * 32 + (lane & 7) + (((lane >> 4) & 1) << 3);
    const int bcol = ((lane >> 3) & 1) << 3;

    #pragma unroll 1
    for (int c = 0; c < DM / 64; c++) {
        const int k0 = c * 64;
        __syncthreads();
        {
            #pragma unroll
            for (int l = 0; l < 12; l++) {
                int i = tid + l * 256;
                if (i < 2048) {
                    int j = i & 1023;
                    int row = j >> 3, seg = j & 7;
                    const __nv_bfloat16* src = (i < 1024) ? g_Xhi : g_Xlo;
                    uint32_t sdst = sb + ((i < 1024) ? PJ_AHI : PJ_ALO) + row * 144 + seg * 16;
                    CPASYNC16(sdst, src + (size_t)(m0 + row) * DM + k0 + seg * 8);
                } else {
                    int j = i - 2048;
                    int lo = j >> 9; j &= 511;
                    int row = j >> 3, seg = j & 7;
                    int off = (lo ? PJ_BLO : PJ_BHI) + row * 144 + seg * 16;
                    if (n0 + row < NALL) {
                        const __nv_bfloat16* src = lo ? g_Wlo : g_Whi;
                        CPASYNC16(sb + off, src + (size_t)(n0 + row) * DM + k0 + seg * 8);
                    } else {
                        *(float4*)(smem + off) = make_float4(0.f, 0.f, 0.f, 0.f);
                    }
                }
            }
        }
        CPCOMMIT();
        CPWAIT0();
        __syncthreads();

        #pragma unroll
        for (int kk = 0; kk < 4; kk++) {
            const int k16 = kk * 16;
            uint32_t ah[8], al[8], bv[8];
            uint32_t aaddr = sb + PJ_AHI + arow * 144 + (k16 + acol) * 2;
            LDSM4(ah[0], ah[1], ah[2], ah[3], aaddr);
            LDSM4(ah[4], ah[5], ah[6], ah[7], aaddr + 16 * 144);
            uint32_t laddr = aaddr + (PJ_ALO - PJ_AHI);
            LDSM4(al[0], al[1], al[2], al[3], laddr);
            LDSM4(al[4], al[5], al[6], al[7], laddr + 16 * 144);
            uint32_t baddr = sb + PJ_BHI + brow * 144 + (k16 + bcol) * 2;
            LDSM4(bv[0], bv[1], bv[2], bv[3], baddr);
            LDSM4(bv[4], bv[5], bv[6], bv[7], baddr + 16 * 144);
            #pragma unroll
            for (int mt = 0; mt < 2; mt++)
                #pragma unroll
                for (int nt = 0; nt < 4; nt++) {
                    MMA16816(facc[mt][nt][0], facc[mt][nt][1], facc[mt][nt][2], facc[mt][nt][3],
                             ah[mt * 4 + 0], ah[mt * 4 + 1], ah[mt * 4 + 2], ah[mt * 4 + 3],
                             bv[nt * 2 + 0], bv[nt * 2 + 1]);
                    MMA16816(facc[mt][nt][0], facc[mt][nt][1], facc[mt][nt][2], facc[mt][nt][3],
                             al[mt * 4 + 0], al[mt * 4 + 1], al[mt * 4 + 2], al[mt * 4 + 3],
                             bv[nt * 2 + 0], bv[nt * 2 + 1]);
                }
            uint32_t bladdr = baddr + (PJ_BLO - PJ_BHI);
            LDSM4(bv[0], bv[1], bv[2], bv[3], bladdr);
            LDSM4(bv[4], bv[5], bv[6], bv[7], bladdr + 16 * 144);
            #pragma unroll
            for (int mt = 0; mt < 2; mt++)
                #pragma unroll
                for (int nt = 0; nt < 4; nt++)
                    MMA16816(facc[mt][nt][0], facc[mt][nt][1], facc[mt][nt][2], facc[mt][nt][3],
                             ah[mt * 4 + 0], ah[mt * 4 + 1], ah[mt * 4 + 2], ah[mt * 4 + 3],
                             bv[nt * 2 + 0], bv[nt * 2 + 1]);
        }
    }

    #pragma unroll
    for (int mt = 0; mt < 2; mt++) {
        #pragma unroll
        for (int half = 0; half < 2; half++) {
            int m = m0 + wm * 32 + mt * 16 + (lane >> 2) + half * 8;
            #pragma unroll
            for (int nt = 0; nt < 4; nt++) {
                int col = n0 + wn * 32 + nt * 8 + (lane & 3) * 2;
                float v0 = facc[mt][nt][half * 2 + 0];
                float v1 = facc[mt][nt][half * 2 + 1];
                if (col < NQ) {
                    __nv_bfloat16 h0 = __float2bfloat16(v0), h1 = __float2bfloat16(v1);
                    size_t o = (size_t)m * NQ + col;
                    *(__nv_bfloat162*)(g_Qhi + o) = __nv_bfloat162(h0, h1);
                    *(__nv_bfloat162*)(g_Qlo + o) =
                        __nv_bfloat162(__float2bfloat16(v0 - __bfloat162float(h0)),
                                       __float2bfloat16(v1 - __bfloat162float(h1)));
                } else if (col < NQ + NK) {
                    __nv_bfloat16 h0 = __float2bfloat16(v0), h1 = __float2bfloat16(v1);
                    size_t o = (size_t)m * NK + (col - NQ);
                    *(__nv_bfloat162*)(g_Khi + o) = __nv_bfloat162(h0, h1);
                    *(__nv_bfloat162*)(g_Klo + o) =
                        __nv_bfloat162(__float2bfloat16(v0 - __bfloat162float(h0)),
                                       __float2bfloat16(v1 - __bfloat162float(h1)));
                } else if (col < NALL) {
                    *(float2*)(g_Wp + (size_t)m * NW + (col - NQ - NK)) = make_float2(v0, v1);
                }
            }
        }
    }
}

// ---------------------------------------------------------------------------
// 4) HMMA attention v2: K resident in smem; Q double-buffered cp.async pipe.
//    42 uniform Q chunks (cols [64c, 64c+64)); phases: A = 2 chunks x 2 d32
//    heads, B = 8 chunks (d64), C = 32 chunks (16 d128 heads x 2).
// ---------------------------------------------------------------------------
#define SM_Q    0                    // 2 stages x (hi 18432 + lo 18432)
#define SM_KHI_ 73728                // 64 x 464B
#define SM_KLO_ 103424
#define SM_WPA  133120               // 128*28*4 = 14336
#define SM_TOT2 147456

__global__ void __launch_bounds__(256, 1)
attn_mma_kernel(float* __restrict__ out) {
    extern __shared__ char smem[];
    const uint32_t sb = smem_u32_of(smem);
    const int tid = threadIdx.x;
    const int wid = tid >> 5;
    const int lane = tid & 31;
    const int b = blockIdx.z;
    const int t0 = blockIdx.x * 128;
    const int s0 = blockIdx.y * 64;
    float* wp_s = (float*)(smem + SM_WPA);

    // wp[t][gh] = probs[t, cfg] * Wproj[t, gh]
    for (int idx = tid; idx < 128 * NW; idx += 256) {
        int tt = idx / NW, gh = idx % NW;
        int cfg = (gh < 4) ? 0 : (gh < 12) ? 1 : 2;
        int row = b * TT + t0 + tt;
        wp_s[tt * NW + gh] = g_probs[row * 3 + cfg] * g_Wp[(size_t)row * NW + gh];
    }

    // K resident load: 64 rows x 224 cols, hi+lo (3584 float4)
    {
        #pragma unroll
        for (int l = 0; l < 14; l++) {
            int i = tid + l * 256;
            int lo = i >= 1792;
            int r = lo ? (i - 1792) : i;
            int row = r / 28, c28 = r % 28;
            const __nv_bfloat16* src = lo ? g_Klo : g_Khi;
            uint32_t dst = sb + (lo ? SM_KLO_ : SM_KHI_) + row * 464 + c28 * 16;
            CPASYNC16(dst, src + (size_t)(b * TT + s0 + row) * NK + c28 * 8);
        }
    }
    // Q chunk 0 into stage 0
    {
        #pragma unroll
        for (int l = 0; l < 8; l++) {
            int i = tid + l * 256;
            int lo = i >> 10;
            int rem = i & 1023;
            int row = rem >> 3, seg = rem & 7;
            const __nv_bfloat16* src = lo ? g_Qlo : g_Qhi;
            uint32_t dst = sb + SM_Q + lo * 18432 + row * 144 + seg * 16;
            CPASYNC16(dst, src + (size_t)(b * TT + t0 + row) * NQ + seg * 8);
        }
    }
    CPCOMMIT();

    const int wm = wid & 3;
    const int wn = wid >> 2;

    float facc[2][4][4];
    #pragma unroll
    for (int mt = 0; mt < 2; mt++)
        #pragma unroll
        for (int nt = 0; nt < 4; nt++)
            #pragma unroll
            for (int j = 0; j < 4; j++) facc[mt][nt][j] = 0.f;

    const int arow = wm * 32 + (lane & 15);
    const int acol = (lane >> 4) << 3;
    const int brow = wn * 32 + (lane & 7) + (((lane >> 4) & 1) << 3);
    const int bcol = ((lane >> 3) & 1) << 3;

    float dacc[2][4][4];

#define ZERO_DACC() do { \
    _Pragma("unroll") for (int mt = 0; mt < 2; mt++) \
    _Pragma("unroll") for (int nt = 0; nt < 4; nt++) \
    _Pragma("unroll") for (int j = 0; j < 4; j++) dacc[mt][nt][j] = 0.f; } while (0)

#define K16STEP(ACOL0, KCOL0) do { \
    uint32_t ah[8], al[8], bv[8]; \
    uint32_t aaddr = qb + arow * 144 + ((ACOL0) + acol) * 2; \
    LDSM4(ah[0], ah[1], ah[2], ah[3], aaddr); \
    LDSM4(ah[4], ah[5], ah[6], ah[7], aaddr + 16 * 144); \
    LDSM4(al[0], al[1], al[2], al[3], aaddr + 18432); \
    LDSM4(al[4], al[5], al[6], al[7], aaddr + 18432 + 16 * 144); \
    uint32_t baddr = sb + SM_KHI_ + brow * 464 + ((KCOL0) + bcol) * 2; \
    LDSM4(bv[0], bv[1], bv[2], bv[3], baddr); \
    LDSM4(bv[4], bv[5], bv[6], bv[7], baddr + 16 * 464); \
    _Pragma("unroll") for (int mt = 0; mt < 2; mt++) \
    _Pragma("unroll") for (int nt = 0; nt < 4; nt++) { \
        MMA16816(dacc[mt][nt][0], dacc[mt][nt][1], dacc[mt][nt][2], dacc[mt][nt][3], \
                 ah[mt * 4 + 0], ah[mt * 4 + 1], ah[mt * 4 + 2], ah[mt * 4 + 3], \
                 bv[nt * 2 + 0], bv[nt * 2 + 1]); \
        MMA16816(dacc[mt][nt][0], dacc[mt][nt][1], dacc[mt][nt][2], dacc[mt][nt][3], \
                 al[mt * 4 + 0], al[mt * 4 + 1], al[mt * 4 + 2], al[mt * 4 + 3], \
                 bv[nt * 2 + 0], bv[nt * 2 + 1]); \
    } \
    LDSM4(bv[0], bv[1], bv[2], bv[3], baddr + (SM_KLO_ - SM_KHI_)); \
    LDSM4(bv[4], bv[5], bv[6], bv[7], baddr + (SM_KLO_ - SM_KHI_) + 16 * 464); \
    _Pragma("unroll") for (int mt = 0; mt < 2; mt++) \
    _Pragma("unroll") for (int nt = 0; nt < 4; nt++) \
        MMA16816(dacc[mt][nt][0], dacc[mt][nt][1], dacc[mt][nt][2], dacc[mt][nt][3], \
                 ah[mt * 4 + 0], ah[mt * 4 + 1], ah[mt * 4 + 2], ah[mt * 4 + 3], \
                 bv[nt * 2 + 0], bv[nt * 2 + 1]); } while (0)

#define EPILOGUE(GH) do { \
    _Pragma("unroll") for (int mt = 0; mt < 2; mt++) { \
        int r0 = wm * 32 + mt * 16 + (lane >> 2); \
        float w0 = wp_s[r0 * NW + (GH)]; \
        float w1 = wp_s[(r0 + 8) * NW + (GH)]; \
        _Pragma("unroll") for (int nt = 0; nt < 4; nt++) { \
            facc[mt][nt][0] += w0 * fmaxf(dacc[mt][nt][0], 0.f); \
            facc[mt][nt][1] += w0 * fmaxf(dacc[mt][nt][1], 0.f); \
            facc[mt][nt][2] += w1 * fmaxf(dacc[mt][nt][2], 0.f); \
            facc[mt][nt][3] += w1 * fmaxf(dacc[mt][nt][3], 0.f); \
        } \
    } } while (0)

    #pragma unroll 1
    for (int c = 0; c < 42; c++) {
        CPWAIT0();
        __syncthreads();
        // prefetch next Q chunk into alternate stage
        if (c + 1 < 42) {
            const size_t qb2 = (size_t)(b * TT + t0) * NQ + (c + 1) * 64;
            uint32_t stbase = sb + SM_Q + ((c + 1) & 1) * 36864;
            #pragma unroll
            for (int l = 0; l < 8; l++) {
                int i = tid + l * 256;
                int lo = i >> 10;
                int rem = i & 1023;
                int row = rem >> 3, seg = rem & 7;
                const __nv_bfloat16* src = lo ? g_Qlo : g_Qhi;
                CPASYNC16(stbase + lo * 18432 + row * 144 + seg * 16,
                          src + qb2 + (size_t)row * NQ + seg * 8);
            }
            CPCOMMIT();
        }

        const uint32_t qb = sb + SM_Q + (c & 1) * 36864;
        if (c < 2) {
            // two d32 heads per chunk; K cols [0,32)
            #pragma unroll
            for (int h2 = 0; h2 < 2; h2++) {
                ZERO_DACC();
                K16STEP(h2 * 32 + 0,  0);
                K16STEP(h2 * 32 + 16, 16);
                EPILOGUE(c * 2 + h2);
            }
        } else if (c < 10) {
            // one d64 head; K cols [32,96)
            ZERO_DACC();
            K16STEP(0,  32);
            K16STEP(16, 48);
            K16STEP(32, 64);
            K16STEP(48, 80);
            EPILOGUE(c + 2);
        } else {
            // d128 heads: 2 chunks per head; K cols [96,224)
            int idx = c - 10;
            int half = idx & 1;
            int kb = 96 + half * 64;
            if (!half) ZERO_DACC();
            K16STEP(0,  kb);
            K16STEP(16, kb + 16);
            K16STEP(32, kb + 32);
            K16STEP(48, kb + 48);
            if (half) EPILOGUE(12 + (idx >> 1));
        }
    }

    // store final tile
    #pragma unroll
    for (int mt = 0; mt < 2; mt++) {
        int row = t0 + wm * 32 + mt * 16 + (lane >> 2);
        #pragma unroll
        for (int nt = 0; nt < 4; nt++) {
            int col = s0 + wn * 32 + nt * 8 + (lane & 3) * 2;
            size_t o0 = (size_t)(b * TT + row) * TT + col;
            *(float2*)(out + o0) = make_float2(facc[mt][nt][0], facc[mt][nt][1]);
            *(float2*)(out + o0 + 8 * TT) = make_float2(facc[mt][nt][2], facc[mt][nt][3]);
        }
    }
}

// ---------------------------------------------------------------------------
extern "C" void kernel_launch(void* const* d_in, const int* in_sizes, int n_in,
                              void* d_out, int out_size) {
    const float* x   = (const float*)d_in[0];
    const float* w1  = (const float*)d_in[1];
    const float* b1  = (const float*)d_in[2];
    const float* w2  = (const float*)d_in[3];
    const float* b2  = (const float*)d_in[4];
    const float* w3  = (const float*)d_in[5];
    const float* b3  = (const float*)d_in[6];
    const float* qw0 = (const float*)d_in[7];
    const float* kw0 = (const float*)d_in[8];
    const float* ww0 = (const float*)d_in[9];
    const float* qw1 = (const float*)d_in[10];
    const float* kw1 = (const float*)d_in[11];
    const float* ww1 = (const float*)d_in[12];
    const float* qw2 = (const float*)d_in[13];
    const float* kw2 = (const float*)d_in[14];
    const float* ww2 = (const float*)d_in[15];
    float* out = (float*)d_out;

    stats_kernel<<<dim3(DM / 256, BB), 256>>>(x);
    selector_kernel<<<BB * TT, 256>>>(x, w1, b1, w2, b2, w3, b3);

    split_kernel<<<BB * TT, 256>>>(x,   0, 0);
    split_kernel<<<128,  256>>>(qw0, 1, 0);
    split_kernel<<<512,  256>>>(qw1, 1, 128);
    split_kernel<<<2048, 256>>>(qw2, 1, 640);
    split_kernel<<<32,   256>>>(kw0, 1, 2688);
    split_kernel<<<64,   256>>>(kw1, 1, 2720);
    split_kernel<<<128,  256>>>(kw2, 1, 2784);
    split_kernel<<<4,    256>>>(ww0, 1, 2912);
    split_kernel<<<8,    256>>>(ww1, 1, 2916);
    split_kernel<<<16,   256>>>(ww2, 1, 2924);

    cudaFuncSetAttribute(proj_mma_kernel, cudaFuncAttributeMaxDynamicSharedMemorySize, PJ_TOTAL);
    proj_mma_kernel<<<dim3(BB * TT / 128, (NALL + 63) / 64), 256, PJ_TOTAL>>>();

    cudaFuncSetAttribute(attn_mma_kernel, cudaFuncAttributeMaxDynamicSharedMemorySize, SM_TOT2);
    attn_mma_kernel<<<dim3(TT / 128, TT / 64, BB), 256, SM_TOT2>>>(out);
}

// round 9
// speedup vs baseline: 3.0461x; 1.0697x over previous
#include <cuda_runtime.h>
#include <cuda_fp16.h>
#include <math.h>
#include <stdint.h>

#define BB 2
#define TT 2048
#define DM 1024
#define NQ 2688   // 4*32 + 8*64 + 16*128
#define NK 224    // 32 + 64 + 128
#define NW 28     // 4 + 8 + 16
#define NALL 2940 // NQ + NK + NW

// ---------------- device scratch (no allocation allowed) --------------------
__device__ float g_mean[BB * DM];
__device__ float g_std[BB * DM];
__device__ float g_probs[BB * TT * 3];
__device__ float g_Wp[(size_t)BB * TT * NW];
__device__ __align__(256) __half g_Qhi[(size_t)BB * TT * NQ];
__device__ __align__(256) __half g_Qlo[(size_t)BB * TT * NQ];
__device__ __align__(256) __half g_Khi[(size_t)BB * TT * NK];
__device__ __align__(256) __half g_Xhi[(size_t)BB * TT * DM];
__device__ __align__(256) __half g_Xlo[(size_t)BB * TT * DM];
__device__ __align__(256) __half g_Whi[(size_t)NALL * DM];
__device__ __align__(256) __half g_Wlo[(size_t)NALL * DM];

// ---------------- portable PTX helpers --------------------------------------
__device__ __forceinline__ uint32_t smem_u32_of(const void* p) {
    uint32_t a;
    asm("{ .reg .u64 t; cvta.to.shared.u64 t, %1; cvt.u32.u64 %0, t; }" : "=r"(a) : "l"(p));
    return a;
}
#define CPASYNC16(s, g) \
    asm volatile("cp.async.cg.shared.global [%0], [%1], 16;" :: "r"(s), "l"(g))
#define CPCOMMIT() asm volatile("cp.async.commit_group;" ::: "memory")
#define CPWAIT0()  asm volatile("cp.async.wait_group 0;" ::: "memory")
#define CPWAIT1()  asm volatile("cp.async.wait_group 1;" ::: "memory")
#define LDSM4(r0, r1, r2, r3, addr) \
    asm volatile("ldmatrix.sync.aligned.m8n8.x4.shared.b16 {%0,%1,%2,%3}, [%4];" \
                 : "=r"(r0), "=r"(r1), "=r"(r2), "=r"(r3) : "r"(addr))
#define MMAF16(d0, d1, d2, d3, a0, a1, a2, a3, b0, b1) \
    asm volatile("mma.sync.aligned.m16n8k16.row.col.f32.f16.f16.f32 " \
                 "{%0,%1,%2,%3}, {%4,%5,%6,%7}, {%8,%9}, {%0,%1,%2,%3};" \
                 : "+f"(d0), "+f"(d1), "+f"(d2), "+f"(d3) \
                 : "r"(a0), "r"(a1), "r"(a2), "r"(a3), "r"(b0), "r"(b1))

// ---------------------------------------------------------------------------
// 1) per-(b,d) mean / unbiased std over T
// ---------------------------------------------------------------------------
__global__ void stats_kernel(const float* __restrict__ x) {
    int d = blockIdx.x * blockDim.x + threadIdx.x;
    int b = blockIdx.y;
    const float* px = x + (size_t)b * TT * DM + d;
    double s = 0.0, s2 = 0.0;
    for (int t = 0; t < TT; t++) {
        double v = (double)px[(size_t)t * DM];
        s += v; s2 += v * v;
    }
    double m = s / (double)TT;
    double var = (s2 - s * s / (double)TT) / (double)(TT - 1);
    if (var < 0.0) var = 0.0;
    g_mean[b * DM + d] = (float)m;
    g_std[b * DM + d] = (float)sqrt(var);
}

// ---------------------------------------------------------------------------
// 2) selector MLP + softmax
// ---------------------------------------------------------------------------
__global__ void selector_kernel(const float* __restrict__ x,
                                const float* __restrict__ w1, const float* __restrict__ b1,
                                const float* __restrict__ w2, const float* __restrict__ b2,
                                const float* __restrict__ w3, const float* __restrict__ b3) {
    __shared__ float feats[DM];
    __shared__ float h1[64];
    __shared__ float h2[64];
    __shared__ float lg[3];
    int row = blockIdx.x;
    int b = row / TT;
    int t = row % TT;
    int tid = threadIdx.x;
    float posv = 0.1f * ((float)t / (float)TT);

    for (int i = tid; i < DM; i += 256)
        feats[i] = x[(size_t)row * DM + i] + g_mean[b * DM + i] + g_std[b * DM + i] + posv;
    __syncthreads();

    int warp = tid >> 5, lane = tid & 31;
    for (int j = warp; j < 64; j += 8) {
        const float* wr = w1 + j * DM;
        float a = 0.f;
        for (int i = lane; i < DM; i += 32) a += feats[i] * wr[i];
        #pragma unroll
        for (int o = 16; o; o >>= 1) a += __shfl_down_sync(0xffffffffu, a, o);
        if (lane == 0) h1[j] = fmaxf(a + b1[j], 0.f);
    }
    __syncthreads();
    for (int j = warp; j < 64; j += 8) {
        const float* wr = w2 + j * 64;
        float a = h1[lane] * wr[lane] + h1[lane + 32] * wr[lane + 32];
        #pragma unroll
        for (int o = 16; o; o >>= 1) a += __shfl_down_sync(0xffffffffu, a, o);
        if (lane == 0) h2[j] = fmaxf(a + b2[j], 0.f);
    }
    __syncthreads();
    if (tid < 3) {
        float a = b3[tid];
        #pragma unroll 8
        for (int i = 0; i < 64; i++) a += h2[i] * w3[tid * 64 + i];
        lg[tid] = a;
    }
    __syncthreads();
    if (tid == 0) {
        float m = fmaxf(lg[0], fmaxf(lg[1], lg[2]));
        float e0 = expf(lg[0] - m), e1 = expf(lg[1] - m), e2 = expf(lg[2] - m);
        float inv = 1.f / (e0 + e1 + e2);
        g_probs[row * 3 + 0] = e0 * inv;
        g_probs[row * 3 + 1] = e1 * inv;
        g_probs[row * 3 + 2] = e2 * inv;
    }
}

// ---------------------------------------------------------------------------
// 3a) split fp32 -> fp16 hi/lo (destination picked by flag inside kernel)
// ---------------------------------------------------------------------------
__global__ void split_kernel(const float* __restrict__ src, int whichDst, int rowOff) {
    __half* dhi = whichDst ? g_Whi : g_Xhi;
    __half* dlo = whichDst ? g_Wlo : g_Xlo;
    int row = blockIdx.x + rowOff;
    int c = threadIdx.x * 4;
    float4 v = *(const float4*)(src + (size_t)blockIdx.x * DM + c);
    __half h0 = __float2half(v.x), h1 = __float2half(v.y);
    __half h2 = __float2half(v.z), h3 = __float2half(v.w);
    __half2* ph = (__half2*)(dhi + (size_t)row * DM + c);
    __half2* pl = (__half2*)(dlo + (size_t)row * DM + c);
    ph[0] = __halves2half2(h0, h1);
    ph[1] = __halves2half2(h2, h3);
    pl[0] = __halves2half2(__float2half(v.x - __half2float(h0)),
                           __float2half(v.y - __half2float(h1)));
    pl[1] = __halves2half2(__float2half(v.z - __half2float(h2)),
                           __float2half(v.w - __half2float(h3)));
}

// ---------------------------------------------------------------------------
// 3b) HMMA projection GEMM (fp16 3-term): C[4096, 2940] = X @ W^T
//     epilogue: cols [0,2688) -> Q fp16 hi/lo; [2688,2912) -> K fp16 (hi only);
//     [2912,2940) -> Wp fp32.
// ---------------------------------------------------------------------------
#define PJ_AHI 0
#define PJ_ALO 18432
#define PJ_BHI 36864
#define PJ_BLO 46080
#define PJ_TOTAL 55296

__global__ void __launch_bounds__(256, 2)
proj_mma_kernel() {
    extern __shared__ char smem[];
    const uint32_t sb = smem_u32_of(smem);
    const int tid = threadIdx.x;
    const int wid = tid >> 5;
    const int lane = tid & 31;
    const int m0 = blockIdx.x * 128;
    const int n0 = blockIdx.y * 64;

    const int wm = wid & 3;
    const int wn = wid >> 2;

    float facc[2][4][4];
    #pragma unroll
    for (int mt = 0; mt < 2; mt++)
        #pragma unroll
        for (int nt = 0; nt < 4; nt++)
            #pragma unroll
            for (int j = 0; j < 4; j++) facc[mt][nt][j] = 0.f;

    const int arow = wm * 32 + (lane & 15);
    const int acol = (lane >> 4) << 3;
    const int brow = wn * 32 + (lane & 7) + (((lane >> 4) & 1) << 3);
    const int bcol = ((lane >> 3) & 1) << 3;

    #pragma unroll 1
    for (int c = 0; c < DM / 64; c++) {
        const int k0 = c * 64;
        __syncthreads();
        {
            #pragma unroll
            for (int l = 0; l < 12; l++) {
                int i = tid + l * 256;
                if (i < 2048) {
                    int j = i & 1023;
                    int row = j >> 3, seg = j & 7;
                    const __half* src = (i < 1024) ? g_Xhi : g_Xlo;
                    uint32_t sdst = sb + ((i < 1024) ? PJ_AHI : PJ_ALO) + row * 144 + seg * 16;
                    CPASYNC16(sdst, src + (size_t)(m0 + row) * DM + k0 + seg * 8);
                } else {
                    int j = i - 2048;
                    int lo = j >> 9; j &= 511;
                    int row = j >> 3, seg = j & 7;
                    int off = (lo ? PJ_BLO : PJ_BHI) + row * 144 + seg * 16;
                    if (n0 + row < NALL) {
                        const __half* src = lo ? g_Wlo : g_Whi;
                        CPASYNC16(sb + off, src + (size_t)(n0 + row) * DM + k0 + seg * 8);
                    } else {
                        *(float4*)(smem + off) = make_float4(0.f, 0.f, 0.f, 0.f);
                    }
                }
            }
        }
        CPCOMMIT();
        CPWAIT0();
        __syncthreads();

        #pragma unroll
        for (int kk = 0; kk < 4; kk++) {
            const int k16 = kk * 16;
            uint32_t ah[8], al[8], bv[8];
            uint32_t aaddr = sb + PJ_AHI + arow * 144 + (k16 + acol) * 2;
            LDSM4(ah[0], ah[1], ah[2], ah[3], aaddr);
            LDSM4(ah[4], ah[5], ah[6], ah[7], aaddr + 16 * 144);
            uint32_t laddr = aaddr + (PJ_ALO - PJ_AHI);
            LDSM4(al[0], al[1], al[2], al[3], laddr);
            LDSM4(al[4], al[5], al[6], al[7], laddr + 16 * 144);
            uint32_t baddr = sb + PJ_BHI + brow * 144 + (k16 + bcol) * 2;
            LDSM4(bv[0], bv[1], bv[2], bv[3], baddr);
            LDSM4(bv[4], bv[5], bv[6], bv[7], baddr + 16 * 144);
            #pragma unroll
            for (int mt = 0; mt < 2; mt++)
                #pragma unroll
                for (int nt = 0; nt < 4; nt++) {
                    MMAF16(facc[mt][nt][0], facc[mt][nt][1], facc[mt][nt][2], facc[mt][nt][3],
                           ah[mt * 4 + 0], ah[mt * 4 + 1], ah[mt * 4 + 2], ah[mt * 4 + 3],
                           bv[nt * 2 + 0], bv[nt * 2 + 1]);
                    MMAF16(facc[mt][nt][0], facc[mt][nt][1], facc[mt][nt][2], facc[mt][nt][3],
                           al[mt * 4 + 0], al[mt * 4 + 1], al[mt * 4 + 2], al[mt * 4 + 3],
                           bv[nt * 2 + 0], bv[nt * 2 + 1]);
                }
            uint32_t bladdr = baddr + (PJ_BLO - PJ_BHI);
            LDSM4(bv[0], bv[1], bv[2], bv[3], bladdr);
            LDSM4(bv[4], bv[5], bv[6], bv[7], bladdr + 16 * 144);
            #pragma unroll
            for (int mt = 0; mt < 2; mt++)
                #pragma unroll
                for (int nt = 0; nt < 4; nt++)
                    MMAF16(facc[mt][nt][0], facc[mt][nt][1], facc[mt][nt][2], facc[mt][nt][3],
                           ah[mt * 4 + 0], ah[mt * 4 + 1], ah[mt * 4 + 2], ah[mt * 4 + 3],
                           bv[nt * 2 + 0], bv[nt * 2 + 1]);
        }
    }

    #pragma unroll
    for (int mt = 0; mt < 2; mt++) {
        #pragma unroll
        for (int half = 0; half < 2; half++) {
            int m = m0 + wm * 32 + mt * 16 + (lane >> 2) + half * 8;
            #pragma unroll
            for (int nt = 0; nt < 4; nt++) {
                int col = n0 + wn * 32 + nt * 8 + (lane & 3) * 2;
                float v0 = facc[mt][nt][half * 2 + 0];
                float v1 = facc[mt][nt][half * 2 + 1];
                if (col < NQ) {
                    __half h0 = __float2half(v0), h1 = __float2half(v1);
                    size_t o = (size_t)m * NQ + col;
                    *(__half2*)(g_Qhi + o) = __halves2half2(h0, h1);
                    *(__half2*)(g_Qlo + o) =
                        __halves2half2(__float2half(v0 - __half2float(h0)),
                                       __float2half(v1 - __half2float(h1)));
                } else if (col < NQ + NK) {
                    size_t o = (size_t)m * NK + (col - NQ);
                    *(__half2*)(g_Khi + o) =
                        __halves2half2(__float2half(v0), __float2half(v1));
                } else if (col < NALL) {
                    *(float2*)(g_Wp + (size_t)m * NW + (col - NQ - NK)) = make_float2(v0, v1);
                }
            }
        }
    }
}

// ---------------------------------------------------------------------------
// 4) HMMA attention (fp16 2-term: Qhi.K + Qlo.K; K truncated to fp16):
//    K resident; Q 3-stage cp.async pipeline; 42 uniform Q chunks.
// ---------------------------------------------------------------------------
#define SM_Q    0                    // 3 stages x (hi 18432 + lo 18432)
#define SM_KHI_ 110592               // 64 x 464B = 29696
#define SM_WPA  140288               // 128*28*4 = 14336
#define SM_TOT2 154624

__global__ void __launch_bounds__(256, 1)
attn_mma_kernel(float* __restrict__ out) {
    extern __shared__ char smem[];
    const uint32_t sb = smem_u32_of(smem);
    const int tid = threadIdx.x;
    const int wid = tid >> 5;
    const int lane = tid & 31;
    const int b = blockIdx.z;
    const int t0 = blockIdx.x * 128;
    const int s0 = blockIdx.y * 64;
    float* wp_s = (float*)(smem + SM_WPA);

    for (int idx = tid; idx < 128 * NW; idx += 256) {
        int tt = idx / NW, gh = idx % NW;
        int cfg = (gh < 4) ? 0 : (gh < 12) ? 1 : 2;
        int row = b * TT + t0 + tt;
        wp_s[tt * NW + gh] = g_probs[row * 3 + cfg] * g_Wp[(size_t)row * NW + gh];
    }

#define LOAD_QCHUNK(CN) do { \
    const size_t qb2 = (size_t)(b * TT + t0) * NQ + (size_t)(CN) * 64; \
    uint32_t stbase = sb + SM_Q + ((CN) % 3) * 36864; \
    _Pragma("unroll") for (int l = 0; l < 8; l++) { \
        int i = tid + l * 256; \
        int lo = i >> 10; int rem = i & 1023; \
        int row = rem >> 3, seg = rem & 7; \
        const __half* src = lo ? g_Qlo : g_Qhi; \
        CPASYNC16(stbase + lo * 18432 + row * 144 + seg * 16, \
                  src + qb2 + (size_t)row * NQ + seg * 8); \
    } } while (0)

    // K resident (hi only): 64 rows x 224 fp16 = 1792 float4
    {
        #pragma unroll
        for (int l = 0; l < 7; l++) {
            int i = tid + l * 256;
            int row = i / 28, c28 = i % 28;
            CPASYNC16(sb + SM_KHI_ + row * 464 + c28 * 16,
                      g_Khi + (size_t)(b * TT + s0 + row) * NK + c28 * 8);
        }
    }
    LOAD_QCHUNK(0);
    CPCOMMIT();
    LOAD_QCHUNK(1);
    CPCOMMIT();

    const int wm = wid & 3;
    const int wn = wid >> 2;

    float facc[2][4][4];
    #pragma unroll
    for (int mt = 0; mt < 2; mt++)
        #pragma unroll
        for (int nt = 0; nt < 4; nt++)
            #pragma unroll
            for (int j = 0; j < 4; j++) facc[mt][nt][j] = 0.f;

    const int arow = wm * 32 + (lane & 15);
    const int acol = (lane >> 4) << 3;
    const int brow = wn * 32 + (lane & 7) + (((lane >> 4) & 1) << 3);
    const int bcol = ((lane >> 3) & 1) << 3;

    float dacc[2][4][4];

#define ZERO_DACC() do { \
    _Pragma("unroll") for (int mt = 0; mt < 2; mt++) \
    _Pragma("unroll") for (int nt = 0; nt < 4; nt++) \
    _Pragma("unroll") for (int j = 0; j < 4; j++) dacc[mt][nt][j] = 0.f; } while (0)

#define K16STEP(ACOL0, KCOL0) do { \
    uint32_t ah[8], al[8], bv[8]; \
    uint32_t aaddr = qb + arow * 144 + ((ACOL0) + acol) * 2; \
    LDSM4(ah[0], ah[1], ah[2], ah[3], aaddr); \
    LDSM4(ah[4], ah[5], ah[6], ah[7], aaddr + 16 * 144); \
    LDSM4(al[0], al[1], al[2], al[3], aaddr + 18432); \
    LDSM4(al[4], al[5], al[6], al[7], aaddr + 18432 + 16 * 144); \
    uint32_t baddr = sb + SM_KHI_ + brow * 464 + ((KCOL0) + bcol) * 2; \
    LDSM4(bv[0], bv[1], bv[2], bv[3], baddr); \
    LDSM4(bv[4], bv[5], bv[6], bv[7], baddr + 16 * 464); \
    _Pragma("unroll") for (int mt = 0; mt < 2; mt++) \
    _Pragma("unroll") for (int nt = 0; nt < 4; nt++) { \
        MMAF16(dacc[mt][nt][0], dacc[mt][nt][1], dacc[mt][nt][2], dacc[mt][nt][3], \
               ah[mt * 4 + 0], ah[mt * 4 + 1], ah[mt * 4 + 2], ah[mt * 4 + 3], \
               bv[nt * 2 + 0], bv[nt * 2 + 1]); \
        MMAF16(dacc[mt][nt][0], dacc[mt][nt][1], dacc[mt][nt][2], dacc[mt][nt][3], \
               al[mt * 4 + 0], al[mt * 4 + 1], al[mt * 4 + 2], al[mt * 4 + 3], \
               bv[nt * 2 + 0], bv[nt * 2 + 1]); \
    } } while (0)

#define EPILOGUE(GH) do { \
    _Pragma("unroll") for (int mt = 0; mt < 2; mt++) { \
        int r0 = wm * 32 + mt * 16 + (lane >> 2); \
        float w0 = wp_s[r0 * NW + (GH)]; \
        float w1 = wp_s[(r0 + 8) * NW + (GH)]; \
        _Pragma("unroll") for (int nt = 0; nt < 4; nt++) { \
            facc[mt][nt][0] += w0 * fmaxf(dacc[mt][nt][0], 0.f); \
            facc[mt][nt][1] += w0 * fmaxf(dacc[mt][nt][1], 0.f); \
            facc[mt][nt][2] += w1 * fmaxf(dacc[mt][nt][2], 0.f); \
            facc[mt][nt][3] += w1 * fmaxf(dacc[mt][nt][3], 0.f); \
        } \
    } } while (0)

    #pragma unroll 1
    for (int c = 0; c < 42; c++) {
        if (c >= 40) { CPWAIT0(); } else { CPWAIT1(); }
        __syncthreads();
        if (c + 2 < 42) { LOAD_QCHUNK(c + 2); CPCOMMIT(); }

        const uint32_t qb = sb + SM_Q + (c % 3) * 36864;
        if (c < 2) {
            // two d32 heads per chunk; K cols [0,32)
            #pragma unroll
            for (int h2 = 0; h2 < 2; h2++) {
                ZERO_DACC();
                K16STEP(h2 * 32 + 0,  0);
                K16STEP(h2 * 32 + 16, 16);
                EPILOGUE(c * 2 + h2);
            }
        } else if (c < 10) {
            // one d64 head; K cols [32,96)
            ZERO_DACC();
            K16STEP(0,  32);
            K16STEP(16, 48);
            K16STEP(32, 64);
            K16STEP(48, 80);
            EPILOGUE(c + 2);
        } else {
            // d128 heads: 2 chunks per head; K cols [96,224)
            int idx = c - 10;
            int half = idx & 1;
            int kb = 96 + half * 64;
            if (!half) ZERO_DACC();
            K16STEP(0,  kb);
            K16STEP(16, kb + 16);
            K16STEP(32, kb + 32);
            K16STEP(48, kb + 48);
            if (half) EPILOGUE(12 + (idx >> 1));
        }
    }

    #pragma unroll
    for (int mt = 0; mt < 2; mt++) {
        int row = t0 + wm * 32 + mt * 16 + (lane >> 2);
        #pragma unroll
        for (int nt = 0; nt < 4; nt++) {
            int col = s0 + wn * 32 + nt * 8 + (lane & 3) * 2;
            size_t o0 = (size_t)(b * TT + row) * TT + col;
            *(float2*)(out + o0) = make_float2(facc[mt][nt][0], facc[mt][nt][1]);
            *(float2*)(out + o0 + 8 * TT) = make_float2(facc[mt][nt][2], facc[mt][nt][3]);
        }
    }
}

// ---------------------------------------------------------------------------
extern "C" void kernel_launch(void* const* d_in, const int* in_sizes, int n_in,
                              void* d_out, int out_size) {
    const float* x   = (const float*)d_in[0];
    const float* w1  = (const float*)d_in[1];
    const float* b1  = (const float*)d_in[2];
    const float* w2  = (const float*)d_in[3];
    const float* b2  = (const float*)d_in[4];
    const float* w3  = (const float*)d_in[5];
    const float* b3  = (const float*)d_in[6];
    const float* qw0 = (const float*)d_in[7];
    const float* kw0 = (const float*)d_in[8];
    const float* ww0 = (const float*)d_in[9];
    const float* qw1 = (const float*)d_in[10];
    const float* kw1 = (const float*)d_in[11];
    const float* ww1 = (const float*)d_in[12];
    const float* qw2 = (const float*)d_in[13];
    const float* kw2 = (const float*)d_in[14];
    const float* ww2 = (const float*)d_in[15];
    float* out = (float*)d_out;

    stats_kernel<<<dim3(DM / 256, BB), 256>>>(x);
    selector_kernel<<<BB * TT, 256>>>(x, w1, b1, w2, b2, w3, b3);

    split_kernel<<<BB * TT, 256>>>(x,   0, 0);
    split_kernel<<<128,  256>>>(qw0, 1, 0);
    split_kernel<<<512,  256>>>(qw1, 1, 128);
    split_kernel<<<2048, 256>>>(qw2, 1, 640);
    split_kernel<<<32,   256>>>(kw0, 1, 2688);
    split_kernel<<<64,   256>>>(kw1, 1, 2720);
    split_kernel<<<128,  256>>>(kw2, 1, 2784);
    split_kernel<<<4,    256>>>(ww0, 1, 2912);
    split_kernel<<<8,    256>>>(ww1, 1, 2916);
    split_kernel<<<16,   256>>>(ww2, 1, 2924);

    cudaFuncSetAttribute(proj_mma_kernel, cudaFuncAttributeMaxDynamicSharedMemorySize, PJ_TOTAL);
    proj_mma_kernel<<<dim3(BB * TT / 128, (NALL + 63) / 64), 256, PJ_TOTAL>>>();

    cudaFuncSetAttribute(attn_mma_kernel, cudaFuncAttributeMaxDynamicSharedMemorySize, SM_TOT2);
    attn_mma_kernel<<<dim3(TT / 128, TT / 64, BB), 256, SM_TOT2>>>(out);
}

// round 10
// speedup vs baseline: 3.1725x; 1.0415x over previous
#include <cuda_runtime.h>
#include <cuda_fp16.h>
#include <math.h>
#include <stdint.h>

#define BB 2
#define TT 2048
#define DM 1024
#define NQ 2688   // 4*32 + 8*64 + 16*128
#define NK 224    // 32 + 64 + 128
#define NW 28     // 4 + 8 + 16
#define NALL 2940 // NQ + NK + NW

// ---------------- device scratch (no allocation allowed) --------------------
__device__ float g_mean[BB * DM];
__device__ float g_std[BB * DM];
__device__ float g_probs[BB * TT * 3];
__device__ float g_Wp[(size_t)BB * TT * NW];
__device__ __align__(256) __half g_Qhi[(size_t)BB * TT * NQ];
__device__ __align__(256) __half g_Qlo[(size_t)BB * TT * NQ];
__device__ __align__(256) __half g_Khi[(size_t)BB * TT * NK];
__device__ __align__(256) __half g_Xhi[(size_t)BB * TT * DM];
__device__ __align__(256) __half g_Xlo[(size_t)BB * TT * DM];
__device__ __align__(256) __half g_Whi[(size_t)NALL * DM];
__device__ __align__(256) __half g_Wlo[(size_t)NALL * DM];

// ---------------- portable PTX helpers --------------------------------------
__device__ __forceinline__ uint32_t smem_u32_of(const void* p) {
    uint32_t a;
    asm("{ .reg .u64 t; cvta.to.shared.u64 t, %1; cvt.u32.u64 %0, t; }" : "=r"(a) : "l"(p));
    return a;
}
#define CPASYNC16(s, g) \
    asm volatile("cp.async.cg.shared.global [%0], [%1], 16;" :: "r"(s), "l"(g))
#define CPCOMMIT() asm volatile("cp.async.commit_group;" ::: "memory")
#define CPWAIT0()  asm volatile("cp.async.wait_group 0;" ::: "memory")
#define CPWAIT1()  asm volatile("cp.async.wait_group 1;" ::: "memory")
#define LDSM4(r0, r1, r2, r3, addr) \
    asm volatile("ldmatrix.sync.aligned.m8n8.x4.shared.b16 {%0,%1,%2,%3}, [%4];" \
                 : "=r"(r0), "=r"(r1), "=r"(r2), "=r"(r3) : "r"(addr))
#define MMAF16(d0, d1, d2, d3, a0, a1, a2, a3, b0, b1) \
    asm volatile("mma.sync.aligned.m16n8k16.row.col.f32.f16.f16.f32 " \
                 "{%0,%1,%2,%3}, {%4,%5,%6,%7}, {%8,%9}, {%0,%1,%2,%3};" \
                 : "+f"(d0), "+f"(d1), "+f"(d2), "+f"(d3) \
                 : "r"(a0), "r"(a1), "r"(a2), "r"(a3), "r"(b0), "r"(b1))

// ---------------------------------------------------------------------------
// 1) per-(b,d) mean / unbiased std over T
// ---------------------------------------------------------------------------
__global__ void stats_kernel(const float* __restrict__ x) {
    int d = blockIdx.x * blockDim.x + threadIdx.x;
    int b = blockIdx.y;
    const float* px = x + (size_t)b * TT * DM + d;
    double s = 0.0, s2 = 0.0;
    for (int t = 0; t < TT; t++) {
        double v = (double)px[(size_t)t * DM];
        s += v; s2 += v * v;
    }
    double m = s / (double)TT;
    double var = (s2 - s * s / (double)TT) / (double)(TT - 1);
    if (var < 0.0) var = 0.0;
    g_mean[b * DM + d] = (float)m;
    g_std[b * DM + d] = (float)sqrt(var);
}

// ---------------------------------------------------------------------------
// 2) selector MLP + softmax
// ---------------------------------------------------------------------------
__global__ void selector_kernel(const float* __restrict__ x,
                                const float* __restrict__ w1, const float* __restrict__ b1,
                                const float* __restrict__ w2, const float* __restrict__ b2,
                                const float* __restrict__ w3, const float* __restrict__ b3) {
    __shared__ float feats[DM];
    __shared__ float h1[64];
    __shared__ float h2[64];
    __shared__ float lg[3];
    int row = blockIdx.x;
    int b = row / TT;
    int t = row % TT;
    int tid = threadIdx.x;
    float posv = 0.1f * ((float)t / (float)TT);

    for (int i = tid; i < DM; i += 256)
        feats[i] = x[(size_t)row * DM + i] + g_mean[b * DM + i] + g_std[b * DM + i] + posv;
    __syncthreads();

    int warp = tid >> 5, lane = tid & 31;
    for (int j = warp; j < 64; j += 8) {
        const float* wr = w1 + j * DM;
        float a = 0.f;
        for (int i = lane; i < DM; i += 32) a += feats[i] * wr[i];
        #pragma unroll
        for (int o = 16; o; o >>= 1) a += __shfl_down_sync(0xffffffffu, a, o);
        if (lane == 0) h1[j] = fmaxf(a + b1[j], 0.f);
    }
    __syncthreads();
    for (int j = warp; j < 64; j += 8) {
        const float* wr = w2 + j * 64;
        float a = h1[lane] * wr[lane] + h1[lane + 32] * wr[lane + 32];
        #pragma unroll
        for (int o = 16; o; o >>= 1) a += __shfl_down_sync(0xffffffffu, a, o);
        if (lane == 0) h2[j] = fmaxf(a + b2[j], 0.f);
    }
    __syncthreads();
    if (tid < 3) {
        float a = b3[tid];
        #pragma unroll 8
        for (int i = 0; i < 64; i++) a += h2[i] * w3[tid * 64 + i];
        lg[tid] = a;
    }
    __syncthreads();
    if (tid == 0) {
        float m = fmaxf(lg[0], fmaxf(lg[1], lg[2]));
        float e0 = expf(lg[0] - m), e1 = expf(lg[1] - m), e2 = expf(lg[2] - m);
        float inv = 1.f / (e0 + e1 + e2);
        g_probs[row * 3 + 0] = e0 * inv;
        g_probs[row * 3 + 1] = e1 * inv;
        g_probs[row * 3 + 2] = e2 * inv;
    }
}

// ---------------------------------------------------------------------------
// 3a) splits (consolidated: 2 launches total so ncu -s 5 lands on attn)
// ---------------------------------------------------------------------------
__device__ __forceinline__ void split_row(const float* srcRow, int dstRow,
                                          __half* dhi, __half* dlo, int tid) {
    int c = tid * 4;
    float4 v = *(const float4*)(srcRow + c);
    __half h0 = __float2half(v.x), h1 = __float2half(v.y);
    __half h2 = __float2half(v.z), h3 = __float2half(v.w);
    __half2* ph = (__half2*)(dhi + (size_t)dstRow * DM + c);
    __half2* pl = (__half2*)(dlo + (size_t)dstRow * DM + c);
    ph[0] = __halves2half2(h0, h1);
    ph[1] = __halves2half2(h2, h3);
    pl[0] = __halves2half2(__float2half(v.x - __half2float(h0)),
                           __float2half(v.y - __half2float(h1)));
    pl[1] = __halves2half2(__float2half(v.z - __half2float(h2)),
                           __float2half(v.w - __half2float(h3)));
}

__global__ void splitX_kernel(const float* __restrict__ x) {
    split_row(x + (size_t)blockIdx.x * DM, blockIdx.x, g_Xhi, g_Xlo, threadIdx.x);
}

__global__ void splitW_kernel(const float* __restrict__ qw0, const float* __restrict__ qw1,
                              const float* __restrict__ qw2, const float* __restrict__ kw0,
                              const float* __restrict__ kw1, const float* __restrict__ kw2,
                              const float* __restrict__ ww0, const float* __restrict__ ww1,
                              const float* __restrict__ ww2) {
    int row = blockIdx.x;
    const float* src; int lr;
    if (row < 128)       { src = qw0; lr = row; }
    else if (row < 640)  { src = qw1; lr = row - 128; }
    else if (row < 2688) { src = qw2; lr = row - 640; }
    else if (row < 2720) { src = kw0; lr = row - 2688; }
    else if (row < 2784) { src = kw1; lr = row - 2720; }
    else if (row < 2912) { src = kw2; lr = row - 2784; }
    else if (row < 2916) { src = ww0; lr = row - 2912; }
    else if (row < 2924) { src = ww1; lr = row - 2916; }
    else                 { src = ww2; lr = row - 2924; }
    split_row(src + (size_t)lr * DM, row, g_Whi, g_Wlo, threadIdx.x);
}

// ---------------------------------------------------------------------------
// 3b) HMMA projection GEMM (fp16 3-term): C[4096, 2940] = X @ W^T
// ---------------------------------------------------------------------------
#define PJ_AHI 0
#define PJ_ALO 18432
#define PJ_BHI 36864
#define PJ_BLO 46080
#define PJ_TOTAL 55296

__global__ void __launch_bounds__(256, 2)
proj_mma_kernel() {
    extern __shared__ char smem[];
    const uint32_t sb = smem_u32_of(smem);
    const int tid = threadIdx.x;
    const int wid = tid >> 5;
    const int lane = tid & 31;
    const int m0 = blockIdx.x * 128;
    const int n0 = blockIdx.y * 64;

    const int wm = wid & 3;
    const int wn = wid >> 2;

    float facc[2][4][4];
    #pragma unroll
    for (int mt = 0; mt < 2; mt++)
        #pragma unroll
        for (int nt = 0; nt < 4; nt++)
            #pragma unroll
            for (int j = 0; j < 4; j++) facc[mt][nt][j] = 0.f;

    const int arow = wm * 32 + (lane & 15);
    const int acol = (lane >> 4) << 3;
    const int brow = wn * 32 + (lane & 7) + (((lane >> 4) & 1) << 3);
    const int bcol = ((lane >> 3) & 1) << 3;

    #pragma unroll 1
    for (int c = 0; c < DM / 64; c++) {
        const int k0 = c * 64;
        __syncthreads();
        {
            #pragma unroll
            for (int l = 0; l < 12; l++) {
                int i = tid + l * 256;
                if (i < 2048) {
                    int j = i & 1023;
                    int row = j >> 3, seg = j & 7;
                    const __half* src = (i < 1024) ? g_Xhi : g_Xlo;
                    uint32_t sdst = sb + ((i < 1024) ? PJ_AHI : PJ_ALO) + row * 144 + seg * 16;
                    CPASYNC16(sdst, src + (size_t)(m0 + row) * DM + k0 + seg * 8);
                } else {
                    int j = i - 2048;
                    int lo = j >> 9; j &= 511;
                    int row = j >> 3, seg = j & 7;
                    int off = (lo ? PJ_BLO : PJ_BHI) + row * 144 + seg * 16;
                    if (n0 + row < NALL) {
                        const __half* src = lo ? g_Wlo : g_Whi;
                        CPASYNC16(sb + off, src + (size_t)(n0 + row) * DM + k0 + seg * 8);
                    } else {
                        *(float4*)(smem + off) = make_float4(0.f, 0.f, 0.f, 0.f);
                    }
                }
            }
        }
        CPCOMMIT();
        CPWAIT0();
        __syncthreads();

        #pragma unroll
        for (int kk = 0; kk < 4; kk++) {
            const int k16 = kk * 16;
            uint32_t ah[8], al[8], bv[8];
            uint32_t aaddr = sb + PJ_AHI + arow * 144 + (k16 + acol) * 2;
            LDSM4(ah[0], ah[1], ah[2], ah[3], aaddr);
            LDSM4(ah[4], ah[5], ah[6], ah[7], aaddr + 16 * 144);
            uint32_t laddr = aaddr + (PJ_ALO - PJ_AHI);
            LDSM4(al[0], al[1], al[2], al[3], laddr);
            LDSM4(al[4], al[5], al[6], al[7], laddr + 16 * 144);
            uint32_t baddr = sb + PJ_BHI + brow * 144 + (k16 + bcol) * 2;
            LDSM4(bv[0], bv[1], bv[2], bv[3], baddr);
            LDSM4(bv[4], bv[5], bv[6], bv[7], baddr + 16 * 144);
            #pragma unroll
            for (int mt = 0; mt < 2; mt++)
                #pragma unroll
                for (int nt = 0; nt < 4; nt++) {
                    MMAF16(facc[mt][nt][0], facc[mt][nt][1], facc[mt][nt][2], facc[mt][nt][3],
                           ah[mt * 4 + 0], ah[mt * 4 + 1], ah[mt * 4 + 2], ah[mt * 4 + 3],
                           bv[nt * 2 + 0], bv[nt * 2 + 1]);
                    MMAF16(facc[mt][nt][0], facc[mt][nt][1], facc[mt][nt][2], facc[mt][nt][3],
                           al[mt * 4 + 0], al[mt * 4 + 1], al[mt * 4 + 2], al[mt * 4 + 3],
                           bv[nt * 2 + 0], bv[nt * 2 + 1]);
                }
            uint32_t bladdr = baddr + (PJ_BLO - PJ_BHI);
            LDSM4(bv[0], bv[1], bv[2], bv[3], bladdr);
            LDSM4(bv[4], bv[5], bv[6], bv[7], bladdr + 16 * 144);
            #pragma unroll
            for (int mt = 0; mt < 2; mt++)
                #pragma unroll
                for (int nt = 0; nt < 4; nt++)
                    MMAF16(facc[mt][nt][0], facc[mt][nt][1], facc[mt][nt][2], facc[mt][nt][3],
                           ah[mt * 4 + 0], ah[mt * 4 + 1], ah[mt * 4 + 2], ah[mt * 4 + 3],
                           bv[nt * 2 + 0], bv[nt * 2 + 1]);
        }
    }

    #pragma unroll
    for (int mt = 0; mt < 2; mt++) {
        #pragma unroll
        for (int half = 0; half < 2; half++) {
            int m = m0 + wm * 32 + mt * 16 + (lane >> 2) + half * 8;
            #pragma unroll
            for (int nt = 0; nt < 4; nt++) {
                int col = n0 + wn * 32 + nt * 8 + (lane & 3) * 2;
                float v0 = facc[mt][nt][half * 2 + 0];
                float v1 = facc[mt][nt][half * 2 + 1];
                if (col < NQ) {
                    __half h0 = __float2half(v0), h1 = __float2half(v1);
                    size_t o = (size_t)m * NQ + col;
                    *(__half2*)(g_Qhi + o) = __halves2half2(h0, h1);
                    *(__half2*)(g_Qlo + o) =
                        __halves2half2(__float2half(v0 - __half2float(h0)),
                                       __float2half(v1 - __half2float(h1)));
                } else if (col < NQ + NK) {
                    size_t o = (size_t)m * NK + (col - NQ);
                    *(__half2*)(g_Khi + o) =
                        __halves2half2(__float2half(v0), __float2half(v1));
                } else if (col < NALL) {
                    *(float2*)(g_Wp + (size_t)m * NW + (col - NQ - NK)) = make_float2(v0, v1);
                }
            }
        }
    }
}

// ---------------------------------------------------------------------------
// 4) HMMA attention (fp16 2-term), 512 threads, 128x128 CTA tile.
//    16 warps in 4(m) x 4(n); warp tile 32x32. K resident (128 rows);
//    Q 3-stage cp.async pipeline over 42 chunks.
// ---------------------------------------------------------------------------
#define SM_Q    0                    // 3 stages x (hi 18432 + lo 18432)
#define SM_KHI_ 110592               // 128 x 464B = 59392
#define SM_WPA  169984               // 128*28*4 = 14336
#define SM_TOT2 184320

__global__ void __launch_bounds__(512, 1)
attn_mma_kernel(float* __restrict__ out) {
    extern __shared__ char smem[];
    const uint32_t sb = smem_u32_of(smem);
    const int tid = threadIdx.x;
    const int wid = tid >> 5;
    const int lane = tid & 31;
    const int b = blockIdx.z;
    const int t0 = blockIdx.x * 128;
    const int s0 = blockIdx.y * 128;
    float* wp_s = (float*)(smem + SM_WPA);

    for (int idx = tid; idx < 128 * NW; idx += 512) {
        int tt = idx / NW, gh = idx % NW;
        int cfg = (gh < 4) ? 0 : (gh < 12) ? 1 : 2;
        int row = b * TT + t0 + tt;
        wp_s[tt * NW + gh] = g_probs[row * 3 + cfg] * g_Wp[(size_t)row * NW + gh];
    }

#define LOAD_QCHUNK(CN) do { \
    const size_t qb2 = (size_t)(b * TT + t0) * NQ + (size_t)(CN) * 64; \
    uint32_t stbase = sb + SM_Q + ((CN) % 3) * 36864; \
    _Pragma("unroll") for (int l = 0; l < 4; l++) { \
        int i = tid + l * 512; \
        int lo = i >> 10; int rem = i & 1023; \
        int row = rem >> 3, seg = rem & 7; \
        const __half* src = lo ? g_Qlo : g_Qhi; \
        CPASYNC16(stbase + lo * 18432 + row * 144 + seg * 16, \
                  src + qb2 + (size_t)row * NQ + seg * 8); \
    } } while (0)

    // K resident (hi only): 128 rows x 224 fp16 = 3584 float4
    {
        #pragma unroll
        for (int l = 0; l < 7; l++) {
            int i = tid + l * 512;
            int row = i / 28, c28 = i % 28;
            CPASYNC16(sb + SM_KHI_ + row * 464 + c28 * 16,
                      g_Khi + (size_t)(b * TT + s0 + row) * NK + c28 * 8);
        }
    }
    LOAD_QCHUNK(0);
    CPCOMMIT();
    LOAD_QCHUNK(1);
    CPCOMMIT();

    const int wm = wid & 3;
    const int wn = wid >> 2;

    float facc[2][4][4];
    #pragma unroll
    for (int mt = 0; mt < 2; mt++)
        #pragma unroll
        for (int nt = 0; nt < 4; nt++)
            #pragma unroll
            for (int j = 0; j < 4; j++) facc[mt][nt][j] = 0.f;

    const int arow = wm * 32 + (lane & 15);
    const int acol = (lane >> 4) << 3;
    const int brow = wn * 32 + (lane & 7) + (((lane >> 4) & 1) << 3);
    const int bcol = ((lane >> 3) & 1) << 3;

    float dacc[2][4][4];

#define ZERO_DACC() do { \
    _Pragma("unroll") for (int mt = 0; mt < 2; mt++) \
    _Pragma("unroll") for (int nt = 0; nt < 4; nt++) \
    _Pragma("unroll") for (int j = 0; j < 4; j++) dacc[mt][nt][j] = 0.f; } while (0)

#define K16STEP(ACOL0, KCOL0) do { \
    uint32_t ah[8], al[8], bv[8]; \
    uint32_t aaddr = qb + arow * 144 + ((ACOL0) + acol) * 2; \
    LDSM4(ah[0], ah[1], ah[2], ah[3], aaddr); \
    LDSM4(ah[4], ah[5], ah[6], ah[7], aaddr + 16 * 144); \
    LDSM4(al[0], al[1], al[2], al[3], aaddr + 18432); \
    LDSM4(al[4], al[5], al[6], al[7], aaddr + 18432 + 16 * 144); \
    uint32_t baddr = sb + SM_KHI_ + brow * 464 + ((KCOL0) + bcol) * 2; \
    LDSM4(bv[0], bv[1], bv[2], bv[3], baddr); \
    LDSM4(bv[4], bv[5], bv[6], bv[7], baddr + 16 * 464); \
    _Pragma("unroll") for (int mt = 0; mt < 2; mt++) \
    _Pragma("unroll") for (int nt = 0; nt < 4; nt++) { \
        MMAF16(dacc[mt][nt][0], dacc[mt][nt][1], dacc[mt][nt][2], dacc[mt][nt][3], \
               ah[mt * 4 + 0], ah[mt * 4 + 1], ah[mt * 4 + 2], ah[mt * 4 + 3], \
               bv[nt * 2 + 0], bv[nt * 2 + 1]); \
        MMAF16(dacc[mt][nt][0], dacc[mt][nt][1], dacc[mt][nt][2], dacc[mt][nt][3], \
               al[mt * 4 + 0], al[mt * 4 + 1], al[mt * 4 + 2], al[mt * 4 + 3], \
               bv[nt * 2 + 0], bv[nt * 2 + 1]); \
    } } while (0)

#define EPILOGUE(GH) do { \
    _Pragma("unroll") for (int mt = 0; mt < 2; mt++) { \
        int r0 = wm * 32 + mt * 16 + (lane >> 2); \
        float w0 = wp_s[r0 * NW + (GH)]; \
        float w1 = wp_s[(r0 + 8) * NW + (GH)]; \
        _Pragma("unroll") for (int nt = 0; nt < 4; nt++) { \
            facc[mt][nt][0] += w0 * fmaxf(dacc[mt][nt][0], 0.f); \
            facc[mt][nt][1] += w0 * fmaxf(dacc[mt][nt][1], 0.f); \
            facc[mt][nt][2] += w1 * fmaxf(dacc[mt][nt][2], 0.f); \
            facc[mt][nt][3] += w1 * fmaxf(dacc[mt][nt][3], 0.f); \
        } \
    } } while (0)

    #pragma unroll 1
    for (int c = 0; c < 42; c++) {
        if (c >= 40) { CPWAIT0(); } else { CPWAIT1(); }
        __syncthreads();
        if (c + 2 < 42) { LOAD_QCHUNK(c + 2); CPCOMMIT(); }

        const uint32_t qb = sb + SM_Q + (c % 3) * 36864;
        if (c < 2) {
            #pragma unroll
            for (int h2 = 0; h2 < 2; h2++) {
                ZERO_DACC();
                K16STEP(h2 * 32 + 0,  0);
                K16STEP(h2 * 32 + 16, 16);
                EPILOGUE(c * 2 + h2);
            }
        } else if (c < 10) {
            ZERO_DACC();
            K16STEP(0,  32);
            K16STEP(16, 48);
            K16STEP(32, 64);
            K16STEP(48, 80);
            EPILOGUE(c + 2);
        } else {
            int idx = c - 10;
            int half = idx & 1;
            int kb = 96 + half * 64;
            if (!half) ZERO_DACC();
            K16STEP(0,  kb);
            K16STEP(16, kb + 16);
            K16STEP(32, kb + 32);
            K16STEP(48, kb + 48);
            if (half) EPILOGUE(12 + (idx >> 1));
        }
    }

    #pragma unroll
    for (int mt = 0; mt < 2; mt++) {
        int row = t0 + wm * 32 + mt * 16 + (lane >> 2);
        #pragma unroll
        for (int nt = 0; nt < 4; nt++) {
            int col = s0 + wn * 32 + nt * 8 + (lane & 3) * 2;
            size_t o0 = (size_t)(b * TT + row) * TT + col;
            *(float2*)(out + o0) = make_float2(facc[mt][nt][0], facc[mt][nt][1]);
            *(float2*)(out + o0 + 8 * TT) = make_float2(facc[mt][nt][2], facc[mt][nt][3]);
        }
    }
}

// ---------------------------------------------------------------------------
extern "C" void kernel_launch(void* const* d_in, const int* in_sizes, int n_in,
                              void* d_out, int out_size) {
    const float* x   = (const float*)d_in[0];
    const float* w1  = (const float*)d_in[1];
    const float* b1  = (const float*)d_in[2];
    const float* w2  = (const float*)d_in[3];
    const float* b2  = (const float*)d_in[4];
    const float* w3  = (const float*)d_in[5];
    const float* b3  = (const float*)d_in[6];
    const float* qw0 = (const float*)d_in[7];
    const float* kw0 = (const float*)d_in[8];
    const float* ww0 = (const float*)d_in[9];
    const float* qw1 = (const float*)d_in[10];
    const float* kw1 = (const float*)d_in[11];
    const float* ww1 = (const float*)d_in[12];
    const float* qw2 = (const float*)d_in[13];
    const float* kw2 = (const float*)d_in[14];
    const float* ww2 = (const float*)d_in[15];
    float* out = (float*)d_out;

    stats_kernel<<<dim3(DM / 256, BB), 256>>>(x);          // launch 1
    selector_kernel<<<BB * TT, 256>>>(x, w1, b1, w2, b2, w3, b3); // 2
    splitX_kernel<<<BB * TT, 256>>>(x);                    // 3
    splitW_kernel<<<NALL, 256>>>(qw0, qw1, qw2, kw0, kw1, kw2, ww0, ww1, ww2); // 4

    cudaFuncSetAttribute(proj_mma_kernel, cudaFuncAttributeMaxDynamicSharedMemorySize, PJ_TOTAL);
    proj_mma_kernel<<<dim3(BB * TT / 128, (NALL + 63) / 64), 256, PJ_TOTAL>>>(); // 5

    cudaFuncSetAttribute(attn_mma_kernel, cudaFuncAttributeMaxDynamicSharedMemorySize, SM_TOT2);
    attn_mma_kernel<<<dim3(TT / 128, TT / 128, BB), 512, SM_TOT2>>>(out);        // 6 <- ncu -s 5
}